// round 1
// baseline (speedup 1.0000x reference)
#include <cuda_runtime.h>

// Problem constants
#define B_  4
#define T_  4096
#define C_  1024
#define H_  64
#define BT_ (B_*T_)

typedef unsigned long long u64;

// Scratch for q, k, v projections (4 MB each) — device globals, no allocation.
__device__ float g_k[(size_t)BT_ * H_];
__device__ float g_q[(size_t)BT_ * H_];
__device__ float g_v[(size_t)BT_ * H_];

// ---------------- packed f32x2 helpers (sm_100+) ----------------
__device__ __forceinline__ u64 ffma2(u64 a, u64 b, u64 c) {
    u64 d;
    asm("fma.rn.f32x2 %0, %1, %2, %3;" : "=l"(d) : "l"(a), "l"(b), "l"(c));
    return d;
}
__device__ __forceinline__ u64 fmul2(u64 a, u64 b) {
    u64 d;
    asm("mul.rn.f32x2 %0, %1, %2;" : "=l"(d) : "l"(a), "l"(b));
    return d;
}
__device__ __forceinline__ u64 splat2(float x) {
    u64 r;
    asm("mov.b64 %0, {%1, %1};" : "=l"(r) : "f"(x));
    return r;
}
__device__ __forceinline__ float2 unpack2(u64 a) {
    float2 f;
    asm("mov.b64 {%0, %1}, %2;" : "=f"(f.x), "=f"(f.y) : "l"(a));
    return f;
}

// =================================================================
// Kernel 1: QKV projection.  out[t][h] = sum_c x[t][c] * W[h][c]
// Grid: (BT_/128, 3)  heads: 0->k, 1->q, 2->v.   256 threads.
// Classic smem-tiled SGEMM, BM=128 BN=64 BK=32, f32x2 accumulators
// paired along M (adjacent rows), B value splatted.
// =================================================================
#define PBM 128
#define PBN 64
#define PBK 32
#define PAS 132   // As row stride (pad for 16B alignment + conflicts)
#define PBS 68    // Bs row stride

__global__ void __launch_bounds__(256) qkv_proj(
    const float* __restrict__ x,
    const float* __restrict__ Wk,
    const float* __restrict__ Wq,
    const float* __restrict__ Wv)
{
    __shared__ __align__(16) float As[PBK][PAS];
    __shared__ __align__(16) float Bs[PBK][PBS];

    const int head = blockIdx.y;
    const float* W = (head == 0) ? Wk : ((head == 1) ? Wq : Wv);
    float* outp    = (head == 0) ? g_k : ((head == 1) ? g_q : g_v);

    const int m0  = blockIdx.x * PBM;
    const int tid = threadIdx.x;
    const int tm  = tid >> 4;   // 0..15  -> 8 rows each
    const int tn  = tid & 15;   // 0..15  -> 4 cols each

    u64 acc[4][4];
#pragma unroll
    for (int i = 0; i < 4; i++)
#pragma unroll
        for (int j = 0; j < 4; j++) acc[i][j] = 0ull;

    for (int k0 = 0; k0 < C_; k0 += PBK) {
        // load A tile 128x32 (transposed into As[k][m])
#pragma unroll
        for (int i = 0; i < 4; i++) {
            int idx = tid + i * 256;           // 0..1023 float4 units
            int r   = idx >> 3;                // row 0..127
            int kk  = (idx & 7) << 2;          // k 0..28
            float4 v4 = *(const float4*)(x + (size_t)(m0 + r) * C_ + k0 + kk);
            As[kk + 0][r] = v4.x; As[kk + 1][r] = v4.y;
            As[kk + 2][r] = v4.z; As[kk + 3][r] = v4.w;
        }
        // load B tile 64x32 (transposed into Bs[k][n])
#pragma unroll
        for (int i = 0; i < 2; i++) {
            int idx = tid + i * 256;           // 0..511
            int n   = idx >> 3;                // 0..63
            int kk  = (idx & 7) << 2;
            float4 v4 = *(const float4*)(W + (size_t)n * C_ + k0 + kk);
            Bs[kk + 0][n] = v4.x; Bs[kk + 1][n] = v4.y;
            Bs[kk + 2][n] = v4.z; Bs[kk + 3][n] = v4.w;
        }
        __syncthreads();

#pragma unroll
        for (int kk = 0; kk < PBK; kk++) {
            const u64* ap = (const u64*)&As[kk][tm * 8];   // 4 row-pairs
            u64 a0 = ap[0], a1 = ap[1], a2 = ap[2], a3 = ap[3];
            float4 b4 = *(const float4*)&Bs[kk][tn * 4];
            u64 b0 = splat2(b4.x), b1 = splat2(b4.y), b2 = splat2(b4.z), b3 = splat2(b4.w);
            acc[0][0] = ffma2(a0, b0, acc[0][0]); acc[0][1] = ffma2(a0, b1, acc[0][1]);
            acc[0][2] = ffma2(a0, b2, acc[0][2]); acc[0][3] = ffma2(a0, b3, acc[0][3]);
            acc[1][0] = ffma2(a1, b0, acc[1][0]); acc[1][1] = ffma2(a1, b1, acc[1][1]);
            acc[1][2] = ffma2(a1, b2, acc[1][2]); acc[1][3] = ffma2(a1, b3, acc[1][3]);
            acc[2][0] = ffma2(a2, b0, acc[2][0]); acc[2][1] = ffma2(a2, b1, acc[2][1]);
            acc[2][2] = ffma2(a2, b2, acc[2][2]); acc[2][3] = ffma2(a2, b3, acc[2][3]);
            acc[3][0] = ffma2(a3, b0, acc[3][0]); acc[3][1] = ffma2(a3, b1, acc[3][1]);
            acc[3][2] = ffma2(a3, b2, acc[3][2]); acc[3][3] = ffma2(a3, b3, acc[3][3]);
        }
        __syncthreads();
    }

    // store: acc[i][j] holds rows (m0+tm*8+2i, +2i+1), col tn*4+j
#pragma unroll
    for (int i = 0; i < 4; i++) {
        float2 u0 = unpack2(acc[i][0]);
        float2 u1 = unpack2(acc[i][1]);
        float2 u2 = unpack2(acc[i][2]);
        float2 u3 = unpack2(acc[i][3]);
        int r = m0 + tm * 8 + 2 * i;
        *(float4*)(outp + (size_t)r * H_ + tn * 4)       = make_float4(u0.x, u1.x, u2.x, u3.x);
        *(float4*)(outp + (size_t)(r + 1) * H_ + tn * 4) = make_float4(u0.y, u1.y, u2.y, u3.y);
    }
}

// =================================================================
// Kernel 2: flash attention with in-CTA split-K over warps.
//   CTA: 32 query rows (one batch), 8 warps. Lane l of every warp
//   owns row m0+l; warp w handles key tiles w, w+8, w+16, ...
//   Each warp keeps its own (m, l, o[64]) partial softmax state,
//   combined at the end via log2(8)=3 smem rounds.
// Mask: key j allowed iff j <= row+1.  Logits = (q.k) / 64 (double scale).
// =================================================================
#define AM 32
#define KT 32
#define NW 8
#define SC2 (1.0f / 64.0f)
#define NEG_BIG (-1e30f)

// smem layout (dynamic, 128 KB):
//   [0,      65536)  : per-warp K tiles (w*8192, 32x64 fp32 each)
//   [65536, 131072)  : per-warp V tiles
// combine stage reuses the K region after the key loop:
//   stage_o : u64 [4][32][33]  (33792 B)
//   stage_m : float[4*32] at +33792
//   stage_l : float[4*32] at +34304
#define ATTN_SMEM 131072

__global__ void __launch_bounds__(256, 1) attn_kernel(float* __restrict__ out)
{
    extern __shared__ __align__(16) char sm[];

    const int tid = threadIdx.x;
    const int w   = tid >> 5;
    const int l   = tid & 31;

    const int nblk = B_ * (T_ / AM);
    const int bid  = (nblk - 1) - blockIdx.x;     // heavy blocks first
    const int mblk = bid / B_;
    const int b    = bid % B_;
    const int m0   = mblk * AM;

    const int row  = m0 + l;                      // this lane's query row
    const int lim  = row + 1;                     // max allowed key index

    // ---- load q row into registers (32 packed pairs) ----
    u64 qq[32];
    {
        const ulonglong2* qg = (const ulonglong2*)(g_q + ((size_t)b * T_ + row) * H_);
#pragma unroll
        for (int i = 0; i < 16; i++) {
            ulonglong2 t = qg[i];
            qq[2 * i] = t.x; qq[2 * i + 1] = t.y;
        }
    }

    u64 oo[32];
#pragma unroll
    for (int h = 0; h < 32; h++) oo[h] = 0ull;
    float mrun = NEG_BIG;
    float lrun = 0.0f;

    const int kmax = min(m0 + AM, T_ - 1);        // highest key any row here needs
    const int nkt  = (kmax >> 5) + 1;             // number of 32-key tiles

    float4* skw = (float4*)(sm + (size_t)w * 8192);
    float4* svw = (float4*)(sm + 65536 + (size_t)w * 8192);
    const ulonglong2* skp = (const ulonglong2*)skw;
    const ulonglong2* svp = (const ulonglong2*)svw;

    for (int t = w; t < nkt; t += NW) {
        const int j0 = t * KT;

        // warp-collective load of K and V tiles (32 rows x 64 fp32 each)
        {
            const float4* kg4 = (const float4*)(g_k + ((size_t)b * T_ + j0) * H_);
            const float4* vg4 = (const float4*)(g_v + ((size_t)b * T_ + j0) * H_);
#pragma unroll
            for (int i = 0; i < 16; i++) {
                skw[l + i * 32] = kg4[l + i * 32];
                svw[l + i * 32] = vg4[l + i * 32];
            }
        }
        __syncwarp();

        if (j0 <= lim) {                          // lane has >=1 valid key in tile
            // ---- scores: s[j] = (q . k_j) / 64 ----
            float s[KT];
#pragma unroll
            for (int jc = 0; jc < KT; jc += 8) {
                u64 acc[8];
#pragma unroll
                for (int j = 0; j < 8; j++) acc[j] = 0ull;
#pragma unroll
                for (int h4 = 0; h4 < 16; h4++) {
                    u64 qa = qq[2 * h4], qb = qq[2 * h4 + 1];
#pragma unroll
                    for (int j = 0; j < 8; j++) {
                        ulonglong2 kv = skp[(jc + j) * 16 + h4];
                        acc[j] = ffma2(qa, kv.x, acc[j]);
                        acc[j] = ffma2(qb, kv.y, acc[j]);
                    }
                }
#pragma unroll
                for (int j = 0; j < 8; j++) {
                    float2 u = unpack2(acc[j]);
                    s[jc + j] = (u.x + u.y) * SC2;
                }
            }

            // ---- mask + online softmax update ----
            float mt = NEG_BIG;
#pragma unroll
            for (int j = 0; j < KT; j++) {
                if (j0 + j > lim) s[j] = NEG_BIG;
                mt = fmaxf(mt, s[j]);
            }
            float mnew = fmaxf(mrun, mt);
            float corr = __expf(mrun - mnew);
            u64 corrp = splat2(corr);
#pragma unroll
            for (int h = 0; h < 32; h++) oo[h] = fmul2(oo[h], corrp);
            float psum = 0.0f;
#pragma unroll
            for (int j = 0; j < KT; j++) {
                float p = __expf(s[j] - mnew);
                s[j] = p;
                psum += p;
            }
            lrun = lrun * corr + psum;
            mrun = mnew;

            // ---- o += p . V ----
#pragma unroll
            for (int j = 0; j < KT; j++) {
                u64 pj = splat2(s[j]);
#pragma unroll
                for (int h4 = 0; h4 < 16; h4++) {
                    ulonglong2 vv = svp[j * 16 + h4];
                    oo[2 * h4]     = ffma2(pj, vv.x, oo[2 * h4]);
                    oo[2 * h4 + 1] = ffma2(pj, vv.y, oo[2 * h4 + 1]);
                }
            }
        }
        __syncwarp();
    }

    // ---- combine 8 warp-partials (tree, 3 rounds via smem) ----
    u64*   st_o = (u64*)sm;                       // [4][32][33]
    float* st_m = (float*)(sm + 33792);           // [4][32]
    float* st_l = (float*)(sm + 34304);           // [4][32]

#pragma unroll
    for (int half = NW / 2; half >= 1; half >>= 1) {
        __syncthreads();
        if (w >= half && w < 2 * half) {
            int dst = w - half;
            st_m[dst * 32 + l] = mrun;
            st_l[dst * 32 + l] = lrun;
            u64* po = st_o + ((size_t)dst * 32 + l) * 33;
#pragma unroll
            for (int h = 0; h < 32; h++) po[h] = oo[h];
        }
        __syncthreads();
        if (w < half) {
            float m2 = st_m[w * 32 + l];
            float l2 = st_l[w * 32 + l];
            float M  = fmaxf(mrun, m2);
            float c1 = __expf(mrun - M);
            float c2 = __expf(m2 - M);
            lrun = lrun * c1 + l2 * c2;
            u64 c1p = splat2(c1), c2p = splat2(c2);
            const u64* po = st_o + ((size_t)w * 32 + l) * 33;
#pragma unroll
            for (int h = 0; h < 32; h++) {
                u64 tv = fmul2(po[h], c2p);
                oo[h] = ffma2(oo[h], c1p, tv);
            }
            mrun = M;
        }
    }

    if (w == 0) {
        float inv = 1.0f / lrun;
        float* orow = out + ((size_t)b * T_ + row) * H_;
#pragma unroll
        for (int h = 0; h < 32; h++) {
            float2 tv = unpack2(oo[h]);
            tv.x *= inv; tv.y *= inv;
            *(float2*)(orow + 2 * h) = tv;
        }
    }
}

// =================================================================
// launch
// =================================================================
extern "C" void kernel_launch(void* const* d_in, const int* in_sizes, int n_in,
                              void* d_out, int out_size)
{
    const float* x  = (const float*)d_in[0];
    const float* Wk = (const float*)d_in[1];
    const float* Wq = (const float*)d_in[2];
    const float* Wv = (const float*)d_in[3];
    float* out = (float*)d_out;

    (void)in_sizes; (void)n_in; (void)out_size;

    cudaFuncSetAttribute(attn_kernel, cudaFuncAttributeMaxDynamicSharedMemorySize, ATTN_SMEM);

    dim3 pgrid(BT_ / PBM, 3);
    qkv_proj<<<pgrid, 256>>>(x, Wk, Wq, Wv);

    attn_kernel<<<B_ * (T_ / AM), 256, ATTN_SMEM>>>(out);
}

// round 3
// speedup vs baseline: 1.6156x; 1.6156x over previous
#include <cuda_runtime.h>
#include <cstdint>

// Problem constants
#define B_  4
#define T_  4096
#define C_  1024
#define H_  64
#define BT_ (B_*T_)

typedef unsigned long long u64;
typedef unsigned int u32;

// Scratch — device globals, no allocation.
__device__ float g_k[(size_t)BT_ * H_];
__device__ float g_q[(size_t)BT_ * H_];
__device__ float g_v[(size_t)BT_ * H_];
__device__ float g_p0[(size_t)BT_ * H_];   // partial O, key-half 0
__device__ float g_p1[(size_t)BT_ * H_];   // partial O, key-half 1
__device__ float g_l0[(size_t)BT_];        // partial lsum, half 0
__device__ float g_l1[(size_t)BT_];        // partial lsum, half 1

// ---------------- packed f32x2 helpers ----------------
__device__ __forceinline__ u64 ffma2(u64 a, u64 b, u64 c) {
    u64 d; asm("fma.rn.f32x2 %0, %1, %2, %3;" : "=l"(d) : "l"(a), "l"(b), "l"(c)); return d;
}
__device__ __forceinline__ u64 splat2(float x) {
    u64 r; asm("mov.b64 %0, {%1, %1};" : "=l"(r) : "f"(x)); return r;
}
__device__ __forceinline__ float2 unpack2(u64 a) {
    float2 f; asm("mov.b64 {%0, %1}, %2;" : "=f"(f.x), "=f"(f.y) : "l"(a)); return f;
}

// =================================================================
// Kernel 1: QKV projection (unchanged — known-good, ~158us).
// =================================================================
#define PBM 128
#define PBK 32
#define PAS 132
#define PBS 68

__global__ void __launch_bounds__(256) qkv_proj(
    const float* __restrict__ x,
    const float* __restrict__ Wk,
    const float* __restrict__ Wq,
    const float* __restrict__ Wv)
{
    __shared__ __align__(16) float As[PBK][PAS];
    __shared__ __align__(16) float Bs[PBK][PBS];

    const int head = blockIdx.y;
    const float* W = (head == 0) ? Wk : ((head == 1) ? Wq : Wv);
    float* outp    = (head == 0) ? g_k : ((head == 1) ? g_q : g_v);

    const int m0  = blockIdx.x * PBM;
    const int tid = threadIdx.x;
    const int tm  = tid >> 4;
    const int tn  = tid & 15;

    u64 acc[4][4];
#pragma unroll
    for (int i = 0; i < 4; i++)
#pragma unroll
        for (int j = 0; j < 4; j++) acc[i][j] = 0ull;

    for (int k0 = 0; k0 < C_; k0 += PBK) {
#pragma unroll
        for (int i = 0; i < 4; i++) {
            int idx = tid + i * 256;
            int r   = idx >> 3;
            int kk  = (idx & 7) << 2;
            float4 v4 = *(const float4*)(x + (size_t)(m0 + r) * C_ + k0 + kk);
            As[kk + 0][r] = v4.x; As[kk + 1][r] = v4.y;
            As[kk + 2][r] = v4.z; As[kk + 3][r] = v4.w;
        }
#pragma unroll
        for (int i = 0; i < 2; i++) {
            int idx = tid + i * 256;
            int n   = idx >> 3;
            int kk  = (idx & 7) << 2;
            float4 v4 = *(const float4*)(W + (size_t)n * C_ + k0 + kk);
            Bs[kk + 0][n] = v4.x; Bs[kk + 1][n] = v4.y;
            Bs[kk + 2][n] = v4.z; Bs[kk + 3][n] = v4.w;
        }
        __syncthreads();

#pragma unroll
        for (int kk = 0; kk < PBK; kk++) {
            const u64* ap = (const u64*)&As[kk][tm * 8];
            u64 a0 = ap[0], a1 = ap[1], a2 = ap[2], a3 = ap[3];
            float4 b4 = *(const float4*)&Bs[kk][tn * 4];
            u64 b0 = splat2(b4.x), b1 = splat2(b4.y), b2 = splat2(b4.z), b3 = splat2(b4.w);
            acc[0][0] = ffma2(a0, b0, acc[0][0]); acc[0][1] = ffma2(a0, b1, acc[0][1]);
            acc[0][2] = ffma2(a0, b2, acc[0][2]); acc[0][3] = ffma2(a0, b3, acc[0][3]);
            acc[1][0] = ffma2(a1, b0, acc[1][0]); acc[1][1] = ffma2(a1, b1, acc[1][1]);
            acc[1][2] = ffma2(a1, b2, acc[1][2]); acc[1][3] = ffma2(a1, b3, acc[1][3]);
            acc[2][0] = ffma2(a2, b0, acc[2][0]); acc[2][1] = ffma2(a2, b1, acc[2][1]);
            acc[2][2] = ffma2(a2, b2, acc[2][2]); acc[2][3] = ffma2(a2, b3, acc[2][3]);
            acc[3][0] = ffma2(a3, b0, acc[3][0]); acc[3][1] = ffma2(a3, b1, acc[3][1]);
            acc[3][2] = ffma2(a3, b2, acc[3][2]); acc[3][3] = ffma2(a3, b3, acc[3][3]);
        }
        __syncthreads();
    }

#pragma unroll
    for (int i = 0; i < 4; i++) {
        float2 u0 = unpack2(acc[i][0]);
        float2 u1 = unpack2(acc[i][1]);
        float2 u2 = unpack2(acc[i][2]);
        float2 u3 = unpack2(acc[i][3]);
        int r = m0 + tm * 8 + 2 * i;
        *(float4*)(outp + (size_t)r * H_ + tn * 4)       = make_float4(u0.x, u1.x, u2.x, u3.x);
        *(float4*)(outp + (size_t)(r + 1) * H_ + tn * 4) = make_float4(u0.y, u1.y, u2.y, u3.y);
    }
}

// =================================================================
// mma.sync helpers (stable PTX — compiles on generic sm_103 target)
// =================================================================
__device__ __forceinline__ u32 f2tf32(float f) {
    u32 u; asm("cvt.rna.tf32.f32 %0, %1;" : "=r"(u) : "f"(f)); return u;
}
__device__ __forceinline__ void mma_tf32(
    float& d0, float& d1, float& d2, float& d3,
    u32 a0, u32 a1, u32 a2, u32 a3, u32 b0, u32 b1)
{
    asm volatile(
        "mma.sync.aligned.m16n8k8.row.col.f32.tf32.tf32.f32 "
        "{%0,%1,%2,%3}, {%4,%5,%6,%7}, {%8,%9}, {%0,%1,%2,%3};"
        : "+f"(d0), "+f"(d1), "+f"(d2), "+f"(d3)
        : "r"(a0), "r"(a1), "r"(a2), "r"(a3), "r"(b0), "r"(b1));
}

// =================================================================
// Kernel 2: attention via mma.sync tf32, no-max softmax, split-K.
//   256 CTAs: (b, mblk, half). 128 queries/CTA, 8 warps x 16 rows.
//   Key tiles of 128; half 0 does tiles [0,h0), half 1 [h0,nkt).
//   S = Q K^T (per warp 16x128), P = exp(S/64) masked, O += P V.
//   P C-frags -> A-frags via intra-quad shuffles. Partial O/lsum
//   written to g_p*/g_l*; combined by norm_out.
// smem: K tile [128][76] tf32, V tile [128][72] tf32 (u32 words).
// =================================================================
#define KSTR 76
#define VSTR 72
#define SMK_WORDS (128 * KSTR)
#define ATTN_SMEM ((SMK_WORDS + 128 * VSTR) * 4)
#define SCEXP (1.0f / 64.0f)

__global__ void __launch_bounds__(256, 2) attn_mma(int dummy)
{
    extern __shared__ u32 smw[];
    u32* smK = smw;
    u32* smV = smw + SMK_WORDS;

    const int tid  = threadIdx.x;
    const int w    = tid >> 5;
    const int lane = tid & 31;
    const int lq   = lane >> 2;     // 0..7 : row-in-16 group
    const int lk   = lane & 3;      // 0..3

    const int part = blockIdx.x & 1;
    const int pid  = blockIdx.x >> 1;
    const int b    = pid & 3;
    const int mblk = 31 - (pid >> 2);      // heavy first
    const int m0   = mblk * 128;

    const int nkt = min(mblk + 2, T_ / 128);
    const int h0  = nkt >> 1;
    const int t_beg = part ? h0 : 0;
    const int t_end = part ? nkt : h0;

    const int qa = m0 + w * 16 + lq;       // rows owned by this thread
    const int qb = qa + 8;
    const int qwmax = m0 + w * 16 + 15;

    // ---- Q fragments in registers (tf32), ks = 0..7 ----
    u32 qf[8][4];
    {
        const float* qp = g_q + ((size_t)b * T_ + qa) * H_ + lk;
#pragma unroll
        for (int ks = 0; ks < 8; ks++) {
            qf[ks][0] = f2tf32(qp[ks * 8]);
            qf[ks][1] = f2tf32(qp[8 * H_ + ks * 8]);
            qf[ks][2] = f2tf32(qp[ks * 8 + 4]);
            qf[ks][3] = f2tf32(qp[8 * H_ + ks * 8 + 4]);
        }
    }

    float oc[8][4];
#pragma unroll
    for (int i = 0; i < 8; i++)
#pragma unroll
        for (int j = 0; j < 4; j++) oc[i][j] = 0.0f;
    float ls_a = 0.0f, ls_b = 0.0f;

    for (int t = t_beg; t < t_end; t++) {
        const int j0 = t * 128;

        // ---- fill K,V tiles (tf32-converted) ----
        {
            const float4* kg = (const float4*)(g_k + ((size_t)b * T_ + j0) * H_);
            const float4* vg = (const float4*)(g_v + ((size_t)b * T_ + j0) * H_);
#pragma unroll
            for (int i = 0; i < 8; i++) {
                int idx = tid + i * 256;           // 0..2047
                int key = idx >> 4;
                int c4  = idx & 15;
                float4 kv = kg[(size_t)key * 16 + c4];
                u32* d = smK + key * KSTR + c4 * 4;
                d[0] = f2tf32(kv.x); d[1] = f2tf32(kv.y);
                d[2] = f2tf32(kv.z); d[3] = f2tf32(kv.w);
                float4 vv = vg[(size_t)key * 16 + c4];
                u32* e = smV + key * VSTR + c4 * 4;
                e[0] = f2tf32(vv.x); e[1] = f2tf32(vv.y);
                e[2] = f2tf32(vv.z); e[3] = f2tf32(vv.w);
            }
        }
        __syncthreads();

        const int ntmax = min(15, (qwmax + 1 - j0) >> 3);
        for (int nt = 0; nt <= ntmax; nt++) {
            // ---- S frag: 16 queries x 8 keys ----
            float s0 = 0, s1 = 0, s2 = 0, s3 = 0;
            const u32* kb = smK + (nt * 8 + lq) * KSTR + lk;
#pragma unroll
            for (int ks = 0; ks < 8; ks++) {
                u32 b0 = kb[ks * 8];
                u32 b1 = kb[ks * 8 + 4];
                mma_tf32(s0, s1, s2, s3, qf[ks][0], qf[ks][1], qf[ks][2], qf[ks][3], b0, b1);
            }

            // ---- mask + exp + lsum ----
            const int jb = j0 + nt * 8 + 2 * lk;
            float p0 = (jb     <= qa + 1) ? __expf(s0 * SCEXP) : 0.0f;
            float p1 = (jb + 1 <= qa + 1) ? __expf(s1 * SCEXP) : 0.0f;
            float p2 = (jb     <= qb + 1) ? __expf(s2 * SCEXP) : 0.0f;
            float p3 = (jb + 1 <= qb + 1) ? __expf(s3 * SCEXP) : 0.0f;
            ls_a += p0 + p1;
            ls_b += p2 + p3;

            u32 sc0 = f2tf32(p0), sc1 = f2tf32(p1);
            u32 sc2 = f2tf32(p2), sc3 = f2tf32(p3);

            // ---- C-frag -> A-frag permutation (intra-quad shuffles) ----
            const int src  = (lane & ~3) | (lk >> 1);
            const int src2 = src + 2;
            u32 t0a = __shfl_sync(0xffffffffu, sc0, src);
            u32 t1a = __shfl_sync(0xffffffffu, sc1, src);
            u32 t2a = __shfl_sync(0xffffffffu, sc2, src);
            u32 t3a = __shfl_sync(0xffffffffu, sc3, src);
            u32 t0b = __shfl_sync(0xffffffffu, sc0, src2);
            u32 t1b = __shfl_sync(0xffffffffu, sc1, src2);
            u32 t2b = __shfl_sync(0xffffffffu, sc2, src2);
            u32 t3b = __shfl_sync(0xffffffffu, sc3, src2);
            const bool odd = (lane & 1);
            u32 pa0 = odd ? t1a : t0a;
            u32 pa1 = odd ? t3a : t2a;
            u32 pa2 = odd ? t1b : t0b;
            u32 pa3 = odd ? t3b : t2b;

            // ---- O += P V for this 8-key chunk ----
            const u32* vb = smV + (nt * 8 + lk) * VSTR + lq;
#pragma unroll
            for (int ot = 0; ot < 8; ot++) {
                u32 b0 = vb[ot * 8];
                u32 b1 = vb[4 * VSTR + ot * 8];
                mma_tf32(oc[ot][0], oc[ot][1], oc[ot][2], oc[ot][3],
                         pa0, pa1, pa2, pa3, b0, b1);
            }
        }
        __syncthreads();
    }

    // ---- write partial lsum (quad reduce) ----
    ls_a += __shfl_xor_sync(0xffffffffu, ls_a, 1);
    ls_a += __shfl_xor_sync(0xffffffffu, ls_a, 2);
    ls_b += __shfl_xor_sync(0xffffffffu, ls_b, 1);
    ls_b += __shfl_xor_sync(0xffffffffu, ls_b, 2);
    float* lp = part ? g_l1 : g_l0;
    if (lk == 0) {
        lp[(size_t)b * T_ + qa] = ls_a;
        lp[(size_t)b * T_ + qb] = ls_b;
    }

    // ---- write partial O ----
    float* pp = part ? g_p1 : g_p0;
    float* ra = pp + ((size_t)b * T_ + qa) * H_ + 2 * lk;
    float* rb = pp + ((size_t)b * T_ + qb) * H_ + 2 * lk;
#pragma unroll
    for (int ot = 0; ot < 8; ot++) {
        *(float2*)(ra + ot * 8) = make_float2(oc[ot][0], oc[ot][1]);
        *(float2*)(rb + ot * 8) = make_float2(oc[ot][2], oc[ot][3]);
    }
    (void)dummy;
}

// =================================================================
// Kernel 3: combine halves + normalize.
// =================================================================
__global__ void __launch_bounds__(256) norm_out(float* __restrict__ out)
{
    int i4 = blockIdx.x * 256 + threadIdx.x;      // float4 index
    int row = i4 >> 4;
    float inv = 1.0f / (g_l0[row] + g_l1[row]);
    float4 a = ((const float4*)g_p0)[i4];
    float4 c = ((const float4*)g_p1)[i4];
    float4 o;
    o.x = (a.x + c.x) * inv;
    o.y = (a.y + c.y) * inv;
    o.z = (a.z + c.z) * inv;
    o.w = (a.w + c.w) * inv;
    ((float4*)out)[i4] = o;
}

// =================================================================
// launch
// =================================================================
extern "C" void kernel_launch(void* const* d_in, const int* in_sizes, int n_in,
                              void* d_out, int out_size)
{
    const float* x  = (const float*)d_in[0];
    const float* Wk = (const float*)d_in[1];
    const float* Wq = (const float*)d_in[2];
    const float* Wv = (const float*)d_in[3];
    float* out = (float*)d_out;

    (void)in_sizes; (void)n_in; (void)out_size;

    cudaFuncSetAttribute(attn_mma, cudaFuncAttributeMaxDynamicSharedMemorySize, ATTN_SMEM);

    dim3 pgrid(BT_ / PBM, 3);
    qkv_proj<<<pgrid, 256>>>(x, Wk, Wq, Wv);

    attn_mma<<<256, 256, ATTN_SMEM>>>(0);

    norm_out<<<(BT_ * H_ / 4) / 256, 256>>>(out);
}

// round 4
// speedup vs baseline: 2.7600x; 1.7083x over previous
#include <cuda_runtime.h>
#include <cstdint>

// Problem constants
#define B_  4
#define T_  4096
#define C_  1024
#define H_  64
#define BT_ (B_*T_)

typedef unsigned long long u64;
typedef unsigned int u32;

// Scratch — device globals, no allocation.
__device__ float g_k[(size_t)BT_ * H_];
__device__ float g_q[(size_t)BT_ * H_];
__device__ float g_v[(size_t)BT_ * H_];
__device__ float g_wt[192 * C_];           // pre-tf32-rounded W (k|q|v rows)
__device__ float g_p0[(size_t)BT_ * H_];   // partial O, key-half 0
__device__ float g_p1[(size_t)BT_ * H_];   // partial O, key-half 1
__device__ float g_l0[(size_t)BT_];        // partial lsum, half 0
__device__ float g_l1[(size_t)BT_];        // partial lsum, half 1

// ---------------- helpers ----------------
__device__ __forceinline__ u32 f2tf32(float f) {
    u32 u; asm("cvt.rna.tf32.f32 %0, %1;" : "=r"(u) : "f"(f)); return u;
}
__device__ __forceinline__ void mma_tf32(
    float& d0, float& d1, float& d2, float& d3,
    u32 a0, u32 a1, u32 a2, u32 a3, u32 b0, u32 b1)
{
    asm volatile(
        "mma.sync.aligned.m16n8k8.row.col.f32.tf32.tf32.f32 "
        "{%0,%1,%2,%3}, {%4,%5,%6,%7}, {%8,%9}, {%0,%1,%2,%3};"
        : "+f"(d0), "+f"(d1), "+f"(d2), "+f"(d3)
        : "r"(a0), "r"(a1), "r"(a2), "r"(a3), "r"(b0), "r"(b1));
}
__device__ __forceinline__ u32 smem_u32(const void* p) {
    u32 a;
    asm("{ .reg .u64 t; cvta.to.shared.u64 t, %1; cvt.u32.u64 %0, t; }" : "=r"(a) : "l"(p));
    return a;
}
#define CP16(dst, src) asm volatile("cp.async.ca.shared.global [%0], [%1], 16;" :: "r"(dst), "l"(src) : "memory")
#define CP_COMMIT()    asm volatile("cp.async.commit_group;" ::: "memory")
#define CP_WAIT0()     asm volatile("cp.async.wait_group 0;" ::: "memory")

// =================================================================
// Kernel 0: pre-round W (Wk|Wq|Wv) to tf32, store concatenated.
// =================================================================
__global__ void __launch_bounds__(256) w_cvt(
    const float* __restrict__ Wk, const float* __restrict__ Wq,
    const float* __restrict__ Wv)
{
    int f = blockIdx.x * 256 + threadIdx.x;       // float4 index, 49152 total
    int head = f >> 14;                            // 16384 float4 per head
    int off  = f & 16383;
    const float4* src = (const float4*)(head == 0 ? Wk : (head == 1 ? Wq : Wv));
    float4 v = src[off];
    uint4 u;
    u.x = f2tf32(v.x); u.y = f2tf32(v.y); u.z = f2tf32(v.z); u.w = f2tf32(v.w);
    ((uint4*)g_wt)[f] = u;
}

// =================================================================
// Kernel 1: fused QKV projection via mma.sync tf32.
//   128 CTAs x (128 rows x 192 cols). 8 warps: (wrow 0..3) x (wcol 0..1),
//   warp = 32 rows x 96 cols. BK=64, double-buffered smem.
//   Outputs stored PRE-ROUNDED to tf32 (attention consumes raw bits).
// =================================================================
#define PXS 68
#define PROJ_STAGE ((128 + 192) * PXS)            // words per stage
#define PROJ_SMEM  (PROJ_STAGE * 2 * 4)           // 174080 bytes

__global__ void __launch_bounds__(256, 1) proj_mma(const float* __restrict__ x)
{
    extern __shared__ u32 psm[];

    const int tid  = threadIdx.x;
    const int w    = tid >> 5;
    const int lane = tid & 31;
    const int lq   = lane >> 2;
    const int lk   = lane & 3;
    const int wrow = w >> 1;      // 0..3
    const int wcol = w & 1;       // 0..1
    const int m0   = blockIdx.x * 128;

    float acc[2][12][4];
#pragma unroll
    for (int mi = 0; mi < 2; mi++)
#pragma unroll
        for (int nt = 0; nt < 12; nt++)
#pragma unroll
            for (int e = 0; e < 4; e++) acc[mi][nt][e] = 0.0f;

    const u32* wt = (const u32*)g_wt;

    // ---- fill helper (macro to keep addresses simple) ----
#define PROJ_FILL(SB, CH) do {                                               \
    u32* xs_ = (SB);                                                         \
    u32  wsa_ = smem_u32((SB) + 128 * PXS);                                  \
    _Pragma("unroll")                                                        \
    for (int i_ = 0; i_ < 12; i_++) {                                        \
        int idx_ = tid + i_ * 256;                                           \
        int r_ = idx_ >> 4, c4_ = idx_ & 15;                                 \
        CP16(wsa_ + (u32)(r_ * PXS + c4_ * 4) * 4,                           \
             (const void*)(wt + (size_t)r_ * C_ + (CH) * 64 + c4_ * 4));     \
    }                                                                        \
    _Pragma("unroll")                                                        \
    for (int i_ = 0; i_ < 8; i_++) {                                         \
        int idx_ = tid + i_ * 256;                                           \
        int r_ = idx_ >> 4, c4_ = idx_ & 15;                                 \
        float4 v_ = *(const float4*)(x + (size_t)(m0 + r_) * C_ + (CH) * 64 + c4_ * 4); \
        uint4 u_;                                                            \
        u_.x = f2tf32(v_.x); u_.y = f2tf32(v_.y);                            \
        u_.z = f2tf32(v_.z); u_.w = f2tf32(v_.w);                            \
        *(uint4*)(xs_ + r_ * PXS + c4_ * 4) = u_;                            \
    }                                                                        \
    CP_COMMIT();                                                             \
} while (0)

    PROJ_FILL(psm, 0);
    CP_WAIT0();
    __syncthreads();

    for (int ch = 0; ch < 16; ch++) {
        const int cur = ch & 1;
        if (ch + 1 < 16) {
            u32* nb = psm + ((ch + 1) & 1) * PROJ_STAGE;
            PROJ_FILL(nb, ch + 1);
        }

        // ---- compute on stage cur ----
        {
            u32* sb = psm + cur * PROJ_STAGE;
            const u32* xbase = sb + (wrow * 32 + lq) * PXS + lk;
            const u32* wbase = sb + 128 * PXS + (wcol * 96 + lq) * PXS + lk;
#pragma unroll
            for (int ks = 0; ks < 8; ks++) {
                u32 a[2][4];
#pragma unroll
                for (int mi = 0; mi < 2; mi++) {
                    a[mi][0] = xbase[(mi * 16    ) * PXS + ks * 8];
                    a[mi][1] = xbase[(mi * 16 + 8) * PXS + ks * 8];
                    a[mi][2] = xbase[(mi * 16    ) * PXS + ks * 8 + 4];
                    a[mi][3] = xbase[(mi * 16 + 8) * PXS + ks * 8 + 4];
                }
#pragma unroll
                for (int nt = 0; nt < 12; nt++) {
                    u32 b0 = wbase[nt * 8 * PXS + ks * 8];
                    u32 b1 = wbase[nt * 8 * PXS + ks * 8 + 4];
                    mma_tf32(acc[0][nt][0], acc[0][nt][1], acc[0][nt][2], acc[0][nt][3],
                             a[0][0], a[0][1], a[0][2], a[0][3], b0, b1);
                    mma_tf32(acc[1][nt][0], acc[1][nt][1], acc[1][nt][2], acc[1][nt][3],
                             a[1][0], a[1][1], a[1][2], a[1][3], b0, b1);
                }
            }
        }
        if (ch + 1 < 16) CP_WAIT0();
        __syncthreads();
    }

    // ---- epilogue: round to tf32, store to g_k/g_q/g_v ----
#pragma unroll
    for (int mi = 0; mi < 2; mi++) {
#pragma unroll
        for (int nt = 0; nt < 12; nt++) {
            int gr = m0 + wrow * 32 + mi * 16 + lq;
            int gh = wcol * 96 + nt * 8 + 2 * lk;
            int head = gh >> 6;
            int hc   = gh & 63;
            float* op = (head == 0) ? g_k : ((head == 1) ? g_q : g_v);
            float v0 = __uint_as_float(f2tf32(acc[mi][nt][0]));
            float v1 = __uint_as_float(f2tf32(acc[mi][nt][1]));
            float v2 = __uint_as_float(f2tf32(acc[mi][nt][2]));
            float v3 = __uint_as_float(f2tf32(acc[mi][nt][3]));
            *(float2*)(op + (size_t)gr * H_ + hc)       = make_float2(v0, v1);
            *(float2*)(op + (size_t)(gr + 8) * H_ + hc) = make_float2(v2, v3);
        }
    }
}

// =================================================================
// Kernel 2: attention via mma.sync tf32 (q/k/v already tf32 bits).
//   256 CTAs: (b, mblk, half). cp.async tile fill, no cvt.
// =================================================================
#define KSTR 76
#define VSTR 72
#define SMK_WORDS (128 * KSTR)
#define ATTN_SMEM ((SMK_WORDS + 128 * VSTR) * 4)
#define SCEXP (1.0f / 64.0f)

__global__ void __launch_bounds__(256, 2) attn_mma(int dummy)
{
    extern __shared__ u32 smw[];
    u32* smK = smw;
    u32* smV = smw + SMK_WORDS;
    const u32 smbK = smem_u32(smK);
    const u32 smbV = smem_u32(smV);

    const int tid  = threadIdx.x;
    const int w    = tid >> 5;
    const int lane = tid & 31;
    const int lq   = lane >> 2;
    const int lk   = lane & 3;

    const int part = blockIdx.x & 1;
    const int pid  = blockIdx.x >> 1;
    const int b    = pid & 3;
    const int mblk = 31 - (pid >> 2);      // heavy first
    const int m0   = mblk * 128;

    const int nkt = min(mblk + 2, T_ / 128);
    const int h0  = nkt >> 1;
    const int t_beg = part ? h0 : 0;
    const int t_end = part ? nkt : h0;

    const int qa = m0 + w * 16 + lq;
    const int qb = qa + 8;
    const int qwmax = m0 + w * 16 + 15;

    // ---- Q fragments (raw bits — pre-rounded tf32) ----
    u32 qf[8][4];
    {
        const u32* qp = (const u32*)(g_q + ((size_t)b * T_ + qa) * H_) + lk;
#pragma unroll
        for (int ks = 0; ks < 8; ks++) {
            qf[ks][0] = qp[ks * 8];
            qf[ks][1] = qp[8 * H_ + ks * 8];
            qf[ks][2] = qp[ks * 8 + 4];
            qf[ks][3] = qp[8 * H_ + ks * 8 + 4];
        }
    }

    float oc[8][4];
#pragma unroll
    for (int i = 0; i < 8; i++)
#pragma unroll
        for (int j = 0; j < 4; j++) oc[i][j] = 0.0f;
    float ls_a = 0.0f, ls_b = 0.0f;

    for (int t = t_beg; t < t_end; t++) {
        const int j0 = t * 128;

        // ---- cp.async tile fill (pure copy, tf32 bits) ----
        {
            const float4* kg = (const float4*)(g_k + ((size_t)b * T_ + j0) * H_);
            const float4* vg = (const float4*)(g_v + ((size_t)b * T_ + j0) * H_);
#pragma unroll
            for (int i = 0; i < 8; i++) {
                int idx = tid + i * 256;
                int key = idx >> 4;
                int c4  = idx & 15;
                CP16(smbK + (u32)(key * KSTR + c4 * 4) * 4,
                     (const void*)(kg + (size_t)key * 16 + c4));
                CP16(smbV + (u32)(key * VSTR + c4 * 4) * 4,
                     (const void*)(vg + (size_t)key * 16 + c4));
            }
            CP_COMMIT();
            CP_WAIT0();
        }
        __syncthreads();

        const int ntmax = min(15, (qwmax + 1 - j0) >> 3);
        for (int nt = 0; nt <= ntmax; nt++) {
            // ---- S frag: 16 queries x 8 keys ----
            float s0 = 0, s1 = 0, s2 = 0, s3 = 0;
            const u32* kb = smK + (nt * 8 + lq) * KSTR + lk;
#pragma unroll
            for (int ks = 0; ks < 8; ks++) {
                u32 b0 = kb[ks * 8];
                u32 b1 = kb[ks * 8 + 4];
                mma_tf32(s0, s1, s2, s3, qf[ks][0], qf[ks][1], qf[ks][2], qf[ks][3], b0, b1);
            }

            // ---- mask + exp + lsum ----
            const int jb = j0 + nt * 8 + 2 * lk;
            float p0 = (jb     <= qa + 1) ? __expf(s0 * SCEXP) : 0.0f;
            float p1 = (jb + 1 <= qa + 1) ? __expf(s1 * SCEXP) : 0.0f;
            float p2 = (jb     <= qb + 1) ? __expf(s2 * SCEXP) : 0.0f;
            float p3 = (jb + 1 <= qb + 1) ? __expf(s3 * SCEXP) : 0.0f;
            ls_a += p0 + p1;
            ls_b += p2 + p3;

            u32 sc0 = f2tf32(p0), sc1 = f2tf32(p1);
            u32 sc2 = f2tf32(p2), sc3 = f2tf32(p3);

            // ---- C-frag -> A-frag permutation ----
            const int src  = (lane & ~3) | (lk >> 1);
            const int src2 = src + 2;
            u32 t0a = __shfl_sync(0xffffffffu, sc0, src);
            u32 t1a = __shfl_sync(0xffffffffu, sc1, src);
            u32 t2a = __shfl_sync(0xffffffffu, sc2, src);
            u32 t3a = __shfl_sync(0xffffffffu, sc3, src);
            u32 t0b = __shfl_sync(0xffffffffu, sc0, src2);
            u32 t1b = __shfl_sync(0xffffffffu, sc1, src2);
            u32 t2b = __shfl_sync(0xffffffffu, sc2, src2);
            u32 t3b = __shfl_sync(0xffffffffu, sc3, src2);
            const bool odd = (lane & 1);
            u32 pa0 = odd ? t1a : t0a;
            u32 pa1 = odd ? t3a : t2a;
            u32 pa2 = odd ? t1b : t0b;
            u32 pa3 = odd ? t3b : t2b;

            // ---- O += P V ----
            const u32* vb = smV + (nt * 8 + lk) * VSTR + lq;
#pragma unroll
            for (int ot = 0; ot < 8; ot++) {
                u32 b0 = vb[ot * 8];
                u32 b1 = vb[4 * VSTR + ot * 8];
                mma_tf32(oc[ot][0], oc[ot][1], oc[ot][2], oc[ot][3],
                         pa0, pa1, pa2, pa3, b0, b1);
            }
        }
        __syncthreads();
    }

    // ---- write partial lsum (quad reduce) ----
    ls_a += __shfl_xor_sync(0xffffffffu, ls_a, 1);
    ls_a += __shfl_xor_sync(0xffffffffu, ls_a, 2);
    ls_b += __shfl_xor_sync(0xffffffffu, ls_b, 1);
    ls_b += __shfl_xor_sync(0xffffffffu, ls_b, 2);
    float* lp = part ? g_l1 : g_l0;
    if (lk == 0) {
        lp[(size_t)b * T_ + qa] = ls_a;
        lp[(size_t)b * T_ + qb] = ls_b;
    }

    // ---- write partial O ----
    float* pp = part ? g_p1 : g_p0;
    float* ra = pp + ((size_t)b * T_ + qa) * H_ + 2 * lk;
    float* rb = pp + ((size_t)b * T_ + qb) * H_ + 2 * lk;
#pragma unroll
    for (int ot = 0; ot < 8; ot++) {
        *(float2*)(ra + ot * 8) = make_float2(oc[ot][0], oc[ot][1]);
        *(float2*)(rb + ot * 8) = make_float2(oc[ot][2], oc[ot][3]);
    }
    (void)dummy;
}

// =================================================================
// Kernel 3: combine halves + normalize.
// =================================================================
__global__ void __launch_bounds__(256) norm_out(float* __restrict__ out)
{
    int i4 = blockIdx.x * 256 + threadIdx.x;
    int row = i4 >> 4;
    float inv = 1.0f / (g_l0[row] + g_l1[row]);
    float4 a = ((const float4*)g_p0)[i4];
    float4 c = ((const float4*)g_p1)[i4];
    float4 o;
    o.x = (a.x + c.x) * inv;
    o.y = (a.y + c.y) * inv;
    o.z = (a.z + c.z) * inv;
    o.w = (a.w + c.w) * inv;
    ((float4*)out)[i4] = o;
}

// =================================================================
// launch
// =================================================================
extern "C" void kernel_launch(void* const* d_in, const int* in_sizes, int n_in,
                              void* d_out, int out_size)
{
    const float* x  = (const float*)d_in[0];
    const float* Wk = (const float*)d_in[1];
    const float* Wq = (const float*)d_in[2];
    const float* Wv = (const float*)d_in[3];
    float* out = (float*)d_out;

    (void)in_sizes; (void)n_in; (void)out_size;

    cudaFuncSetAttribute(proj_mma, cudaFuncAttributeMaxDynamicSharedMemorySize, PROJ_SMEM);
    cudaFuncSetAttribute(attn_mma, cudaFuncAttributeMaxDynamicSharedMemorySize, ATTN_SMEM);

    w_cvt<<<192, 256>>>(Wk, Wq, Wv);
    proj_mma<<<BT_ / 128, 256, PROJ_SMEM>>>(x);
    attn_mma<<<256, 256, ATTN_SMEM>>>(0);
    norm_out<<<(BT_ * H_ / 4) / 256, 256>>>(out);
}

// round 5
// speedup vs baseline: 3.4022x; 1.2327x over previous
#include <cuda_runtime.h>
#include <cstdint>

// Problem constants
#define B_  4
#define T_  4096
#define C_  1024
#define H_  64
#define BT_ (B_*T_)

typedef unsigned long long u64;
typedef unsigned int u32;

// Scratch — device globals, no allocation.
__device__ float g_k[(size_t)BT_ * H_];
__device__ float g_q[(size_t)BT_ * H_];
__device__ float g_v[(size_t)BT_ * H_];
__device__ float g_wt[192 * C_];            // pre-tf32-rounded W (k|q|v rows)
__device__ float g_p[4][(size_t)BT_ * H_];  // partial O per key-quarter
__device__ float g_l[4][(size_t)BT_];       // partial lsum per key-quarter

// ---------------- helpers ----------------
__device__ __forceinline__ u32 f2tf32(float f) {
    u32 u; asm("cvt.rna.tf32.f32 %0, %1;" : "=r"(u) : "f"(f)); return u;
}
__device__ __forceinline__ void mma_tf32(
    float& d0, float& d1, float& d2, float& d3,
    u32 a0, u32 a1, u32 a2, u32 a3, u32 b0, u32 b1)
{
    asm volatile(
        "mma.sync.aligned.m16n8k8.row.col.f32.tf32.tf32.f32 "
        "{%0,%1,%2,%3}, {%4,%5,%6,%7}, {%8,%9}, {%0,%1,%2,%3};"
        : "+f"(d0), "+f"(d1), "+f"(d2), "+f"(d3)
        : "r"(a0), "r"(a1), "r"(a2), "r"(a3), "r"(b0), "r"(b1));
}
__device__ __forceinline__ u32 smem_u32(const void* p) {
    u32 a;
    asm("{ .reg .u64 t; cvta.to.shared.u64 t, %1; cvt.u32.u64 %0, t; }" : "=r"(a) : "l"(p));
    return a;
}
#define CP16(dst, src) asm volatile("cp.async.ca.shared.global [%0], [%1], 16;" :: "r"(dst), "l"(src) : "memory")
#define CP_COMMIT()    asm volatile("cp.async.commit_group;" ::: "memory")
#define CP_WAIT0()     asm volatile("cp.async.wait_group 0;" ::: "memory")

// =================================================================
// Kernel 0: pre-round W (Wk|Wq|Wv) to tf32, store concatenated.
// =================================================================
__global__ void __launch_bounds__(256) w_cvt(
    const float* __restrict__ Wk, const float* __restrict__ Wq,
    const float* __restrict__ Wv)
{
    int f = blockIdx.x * 256 + threadIdx.x;
    int head = f >> 14;
    int off  = f & 16383;
    const float4* src = (const float4*)(head == 0 ? Wk : (head == 1 ? Wq : Wv));
    float4 v = src[off];
    uint4 u;
    u.x = f2tf32(v.x); u.y = f2tf32(v.y); u.z = f2tf32(v.z); u.w = f2tf32(v.w);
    ((uint4*)g_wt)[f] = u;
}

// =================================================================
// Kernel 1: fused QKV projection via mma.sync tf32 (unchanged).
// =================================================================
#define PXS 68
#define PROJ_STAGE ((128 + 192) * PXS)
#define PROJ_SMEM  (PROJ_STAGE * 2 * 4)

__global__ void __launch_bounds__(256, 1) proj_mma(const float* __restrict__ x)
{
    extern __shared__ u32 psm[];

    const int tid  = threadIdx.x;
    const int w    = tid >> 5;
    const int lane = tid & 31;
    const int lq   = lane >> 2;
    const int lk   = lane & 3;
    const int wrow = w >> 1;
    const int wcol = w & 1;
    const int m0   = blockIdx.x * 128;

    float acc[2][12][4];
#pragma unroll
    for (int mi = 0; mi < 2; mi++)
#pragma unroll
        for (int nt = 0; nt < 12; nt++)
#pragma unroll
            for (int e = 0; e < 4; e++) acc[mi][nt][e] = 0.0f;

    const u32* wt = (const u32*)g_wt;

#define PROJ_FILL(SB, CH) do {                                               \
    u32* xs_ = (SB);                                                         \
    u32  wsa_ = smem_u32((SB) + 128 * PXS);                                  \
    _Pragma("unroll")                                                        \
    for (int i_ = 0; i_ < 12; i_++) {                                        \
        int idx_ = tid + i_ * 256;                                           \
        int r_ = idx_ >> 4, c4_ = idx_ & 15;                                 \
        CP16(wsa_ + (u32)(r_ * PXS + c4_ * 4) * 4,                           \
             (const void*)(wt + (size_t)r_ * C_ + (CH) * 64 + c4_ * 4));     \
    }                                                                        \
    _Pragma("unroll")                                                        \
    for (int i_ = 0; i_ < 8; i_++) {                                         \
        int idx_ = tid + i_ * 256;                                           \
        int r_ = idx_ >> 4, c4_ = idx_ & 15;                                 \
        float4 v_ = *(const float4*)(x + (size_t)(m0 + r_) * C_ + (CH) * 64 + c4_ * 4); \
        uint4 u_;                                                            \
        u_.x = f2tf32(v_.x); u_.y = f2tf32(v_.y);                            \
        u_.z = f2tf32(v_.z); u_.w = f2tf32(v_.w);                            \
        *(uint4*)(xs_ + r_ * PXS + c4_ * 4) = u_;                            \
    }                                                                        \
    CP_COMMIT();                                                             \
} while (0)

    PROJ_FILL(psm, 0);
    CP_WAIT0();
    __syncthreads();

    for (int ch = 0; ch < 16; ch++) {
        const int cur = ch & 1;
        if (ch + 1 < 16) {
            u32* nb = psm + ((ch + 1) & 1) * PROJ_STAGE;
            PROJ_FILL(nb, ch + 1);
        }
        {
            u32* sb = psm + cur * PROJ_STAGE;
            const u32* xbase = sb + (wrow * 32 + lq) * PXS + lk;
            const u32* wbase = sb + 128 * PXS + (wcol * 96 + lq) * PXS + lk;
#pragma unroll
            for (int ks = 0; ks < 8; ks++) {
                u32 a[2][4];
#pragma unroll
                for (int mi = 0; mi < 2; mi++) {
                    a[mi][0] = xbase[(mi * 16    ) * PXS + ks * 8];
                    a[mi][1] = xbase[(mi * 16 + 8) * PXS + ks * 8];
                    a[mi][2] = xbase[(mi * 16    ) * PXS + ks * 8 + 4];
                    a[mi][3] = xbase[(mi * 16 + 8) * PXS + ks * 8 + 4];
                }
#pragma unroll
                for (int nt = 0; nt < 12; nt++) {
                    u32 b0 = wbase[nt * 8 * PXS + ks * 8];
                    u32 b1 = wbase[nt * 8 * PXS + ks * 8 + 4];
                    mma_tf32(acc[0][nt][0], acc[0][nt][1], acc[0][nt][2], acc[0][nt][3],
                             a[0][0], a[0][1], a[0][2], a[0][3], b0, b1);
                    mma_tf32(acc[1][nt][0], acc[1][nt][1], acc[1][nt][2], acc[1][nt][3],
                             a[1][0], a[1][1], a[1][2], a[1][3], b0, b1);
                }
            }
        }
        if (ch + 1 < 16) CP_WAIT0();
        __syncthreads();
    }

#pragma unroll
    for (int mi = 0; mi < 2; mi++) {
#pragma unroll
        for (int nt = 0; nt < 12; nt++) {
            int gr = m0 + wrow * 32 + mi * 16 + lq;
            int gh = wcol * 96 + nt * 8 + 2 * lk;
            int head = gh >> 6;
            int hc   = gh & 63;
            float* op = (head == 0) ? g_k : ((head == 1) ? g_q : g_v);
            float v0 = __uint_as_float(f2tf32(acc[mi][nt][0]));
            float v1 = __uint_as_float(f2tf32(acc[mi][nt][1]));
            float v2 = __uint_as_float(f2tf32(acc[mi][nt][2]));
            float v3 = __uint_as_float(f2tf32(acc[mi][nt][3]));
            *(float2*)(op + (size_t)gr * H_ + hc)       = make_float2(v0, v1);
            *(float2*)(op + (size_t)(gr + 8) * H_ + hc) = make_float2(v2, v3);
        }
    }
}

// =================================================================
// Kernel 2: attention, 4-way split-K for load balance.
//   512 CTAs: (b, mblk, quarter). Heavy mblk first.
// =================================================================
#define KSTR 76
#define VSTR 72
#define SMK_WORDS (128 * KSTR)
#define ATTN_SMEM ((SMK_WORDS + 128 * VSTR) * 4)
#define SCEXP (1.0f / 64.0f)

__global__ void __launch_bounds__(256, 2) attn_mma(int dummy)
{
    extern __shared__ u32 smw[];
    u32* smK = smw;
    u32* smV = smw + SMK_WORDS;
    const u32 smbK = smem_u32(smK);
    const u32 smbV = smem_u32(smV);

    const int tid  = threadIdx.x;
    const int w    = tid >> 5;
    const int lane = tid & 31;
    const int lq   = lane >> 2;
    const int lk   = lane & 3;

    const int part = blockIdx.x & 3;
    const int pid  = blockIdx.x >> 2;
    const int b    = pid & 3;
    const int mblk = 31 - (pid >> 2);      // heavy first
    const int m0   = mblk * 128;

    const int nkt = min(mblk + 2, T_ / 128);
    const int t_beg = (nkt * part) >> 2;
    const int t_end = (nkt * (part + 1)) >> 2;

    const int qa = m0 + w * 16 + lq;
    const int qb = qa + 8;
    const int qwmax = m0 + w * 16 + 15;

    // ---- Q fragments (raw bits — pre-rounded tf32) ----
    u32 qf[8][4];
    {
        const u32* qp = (const u32*)(g_q + ((size_t)b * T_ + qa) * H_) + lk;
#pragma unroll
        for (int ks = 0; ks < 8; ks++) {
            qf[ks][0] = qp[ks * 8];
            qf[ks][1] = qp[8 * H_ + ks * 8];
            qf[ks][2] = qp[ks * 8 + 4];
            qf[ks][3] = qp[8 * H_ + ks * 8 + 4];
        }
    }

    float oc[8][4];
#pragma unroll
    for (int i = 0; i < 8; i++)
#pragma unroll
        for (int j = 0; j < 4; j++) oc[i][j] = 0.0f;
    float ls_a = 0.0f, ls_b = 0.0f;

    for (int t = t_beg; t < t_end; t++) {
        const int j0 = t * 128;

        // ---- cp.async tile fill ----
        {
            const float4* kg = (const float4*)(g_k + ((size_t)b * T_ + j0) * H_);
            const float4* vg = (const float4*)(g_v + ((size_t)b * T_ + j0) * H_);
#pragma unroll
            for (int i = 0; i < 8; i++) {
                int idx = tid + i * 256;
                int key = idx >> 4;
                int c4  = idx & 15;
                CP16(smbK + (u32)(key * KSTR + c4 * 4) * 4,
                     (const void*)(kg + (size_t)key * 16 + c4));
                CP16(smbV + (u32)(key * VSTR + c4 * 4) * 4,
                     (const void*)(vg + (size_t)key * 16 + c4));
            }
            CP_COMMIT();
            CP_WAIT0();
        }
        __syncthreads();

        const int ntmax = min(15, (qwmax + 1 - j0) >> 3);
        for (int nt = 0; nt <= ntmax; nt++) {
            float s0 = 0, s1 = 0, s2 = 0, s3 = 0;
            const u32* kb = smK + (nt * 8 + lq) * KSTR + lk;
#pragma unroll
            for (int ks = 0; ks < 8; ks++) {
                u32 b0 = kb[ks * 8];
                u32 b1 = kb[ks * 8 + 4];
                mma_tf32(s0, s1, s2, s3, qf[ks][0], qf[ks][1], qf[ks][2], qf[ks][3], b0, b1);
            }

            const int jb = j0 + nt * 8 + 2 * lk;
            float p0 = (jb     <= qa + 1) ? __expf(s0 * SCEXP) : 0.0f;
            float p1 = (jb + 1 <= qa + 1) ? __expf(s1 * SCEXP) : 0.0f;
            float p2 = (jb     <= qb + 1) ? __expf(s2 * SCEXP) : 0.0f;
            float p3 = (jb + 1 <= qb + 1) ? __expf(s3 * SCEXP) : 0.0f;
            ls_a += p0 + p1;
            ls_b += p2 + p3;

            u32 sc0 = f2tf32(p0), sc1 = f2tf32(p1);
            u32 sc2 = f2tf32(p2), sc3 = f2tf32(p3);

            const int src  = (lane & ~3) | (lk >> 1);
            const int src2 = src + 2;
            u32 t0a = __shfl_sync(0xffffffffu, sc0, src);
            u32 t1a = __shfl_sync(0xffffffffu, sc1, src);
            u32 t2a = __shfl_sync(0xffffffffu, sc2, src);
            u32 t3a = __shfl_sync(0xffffffffu, sc3, src);
            u32 t0b = __shfl_sync(0xffffffffu, sc0, src2);
            u32 t1b = __shfl_sync(0xffffffffu, sc1, src2);
            u32 t2b = __shfl_sync(0xffffffffu, sc2, src2);
            u32 t3b = __shfl_sync(0xffffffffu, sc3, src2);
            const bool odd = (lane & 1);
            u32 pa0 = odd ? t1a : t0a;
            u32 pa1 = odd ? t3a : t2a;
            u32 pa2 = odd ? t1b : t0b;
            u32 pa3 = odd ? t3b : t2b;

            const u32* vb = smV + (nt * 8 + lk) * VSTR + lq;
#pragma unroll
            for (int ot = 0; ot < 8; ot++) {
                u32 b0 = vb[ot * 8];
                u32 b1 = vb[4 * VSTR + ot * 8];
                mma_tf32(oc[ot][0], oc[ot][1], oc[ot][2], oc[ot][3],
                         pa0, pa1, pa2, pa3, b0, b1);
            }
        }
        __syncthreads();
    }

    // ---- write partial lsum (quad reduce); zeros if no tiles ----
    ls_a += __shfl_xor_sync(0xffffffffu, ls_a, 1);
    ls_a += __shfl_xor_sync(0xffffffffu, ls_a, 2);
    ls_b += __shfl_xor_sync(0xffffffffu, ls_b, 1);
    ls_b += __shfl_xor_sync(0xffffffffu, ls_b, 2);
    float* lp = g_l[part];
    if (lk == 0) {
        lp[(size_t)b * T_ + qa] = ls_a;
        lp[(size_t)b * T_ + qb] = ls_b;
    }

    // ---- write partial O (zeros if no tiles) ----
    float* pp = g_p[part];
    float* ra = pp + ((size_t)b * T_ + qa) * H_ + 2 * lk;
    float* rb = pp + ((size_t)b * T_ + qb) * H_ + 2 * lk;
#pragma unroll
    for (int ot = 0; ot < 8; ot++) {
        *(float2*)(ra + ot * 8) = make_float2(oc[ot][0], oc[ot][1]);
        *(float2*)(rb + ot * 8) = make_float2(oc[ot][2], oc[ot][3]);
    }
    (void)dummy;
}

// =================================================================
// Kernel 3: combine 4 quarters + normalize.
// =================================================================
__global__ void __launch_bounds__(256) norm_out(float* __restrict__ out)
{
    int i4 = blockIdx.x * 256 + threadIdx.x;
    int row = i4 >> 4;
    float inv = 1.0f / (g_l[0][row] + g_l[1][row] + g_l[2][row] + g_l[3][row]);
    float4 a = ((const float4*)g_p[0])[i4];
    float4 c = ((const float4*)g_p[1])[i4];
    float4 d = ((const float4*)g_p[2])[i4];
    float4 e = ((const float4*)g_p[3])[i4];
    float4 o;
    o.x = (a.x + c.x + d.x + e.x) * inv;
    o.y = (a.y + c.y + d.y + e.y) * inv;
    o.z = (a.z + c.z + d.z + e.z) * inv;
    o.w = (a.w + c.w + d.w + e.w) * inv;
    ((float4*)out)[i4] = o;
}

// =================================================================
// launch
// =================================================================
extern "C" void kernel_launch(void* const* d_in, const int* in_sizes, int n_in,
                              void* d_out, int out_size)
{
    const float* x  = (const float*)d_in[0];
    const float* Wk = (const float*)d_in[1];
    const float* Wq = (const float*)d_in[2];
    const float* Wv = (const float*)d_in[3];
    float* out = (float*)d_out;

    (void)in_sizes; (void)n_in; (void)out_size;

    cudaFuncSetAttribute(proj_mma, cudaFuncAttributeMaxDynamicSharedMemorySize, PROJ_SMEM);
    cudaFuncSetAttribute(attn_mma, cudaFuncAttributeMaxDynamicSharedMemorySize, ATTN_SMEM);

    w_cvt<<<192, 256>>>(Wk, Wq, Wv);
    proj_mma<<<BT_ / 128, 256, PROJ_SMEM>>>(x);
    attn_mma<<<512, 256, ATTN_SMEM>>>(0);
    norm_out<<<(BT_ * H_ / 4) / 256, 256>>>(out);
}

// round 6
// speedup vs baseline: 3.4205x; 1.0054x over previous
#include <cuda_runtime.h>
#include <cstdint>

// Problem constants
#define B_  4
#define T_  4096
#define C_  1024
#define H_  64
#define BT_ (B_*T_)

typedef unsigned long long u64;
typedef unsigned int u32;

// Scratch — device globals, no allocation.
__device__ float g_k[(size_t)BT_ * H_];
__device__ float g_q[(size_t)BT_ * H_];
__device__ float g_v[(size_t)BT_ * H_];
__device__ float g_wt[192 * C_];            // pre-tf32-rounded W (k|q|v rows)
__device__ float g_p[4][(size_t)BT_ * H_];  // partial O per key-quarter
__device__ float g_l[4][(size_t)BT_];       // partial lsum per key-quarter

// ---------------- helpers ----------------
__device__ __forceinline__ u32 f2tf32(float f) {
    u32 u; asm("cvt.rna.tf32.f32 %0, %1;" : "=r"(u) : "f"(f)); return u;
}
__device__ __forceinline__ void mma_tf32(
    float& d0, float& d1, float& d2, float& d3,
    u32 a0, u32 a1, u32 a2, u32 a3, u32 b0, u32 b1)
{
    asm volatile(
        "mma.sync.aligned.m16n8k8.row.col.f32.tf32.tf32.f32 "
        "{%0,%1,%2,%3}, {%4,%5,%6,%7}, {%8,%9}, {%0,%1,%2,%3};"
        : "+f"(d0), "+f"(d1), "+f"(d2), "+f"(d3)
        : "r"(a0), "r"(a1), "r"(a2), "r"(a3), "r"(b0), "r"(b1));
}
__device__ __forceinline__ u32 smem_u32(const void* p) {
    u32 a;
    asm("{ .reg .u64 t; cvta.to.shared.u64 t, %1; cvt.u32.u64 %0, t; }" : "=r"(a) : "l"(p));
    return a;
}
#define CP16(dst, src) asm volatile("cp.async.ca.shared.global [%0], [%1], 16;" :: "r"(dst), "l"(src) : "memory")
#define CP_COMMIT()    asm volatile("cp.async.commit_group;" ::: "memory")
#define CP_WAIT0()     asm volatile("cp.async.wait_group 0;" ::: "memory")
#define CP_WAIT1()     asm volatile("cp.async.wait_group 1;" ::: "memory")

// =================================================================
// Kernel 0: pre-round W (Wk|Wq|Wv) to tf32, store concatenated.
// =================================================================
__global__ void __launch_bounds__(256) w_cvt(
    const float* __restrict__ Wk, const float* __restrict__ Wq,
    const float* __restrict__ Wv)
{
    int f = blockIdx.x * 256 + threadIdx.x;
    int head = f >> 14;
    int off  = f & 16383;
    const float4* src = (const float4*)(head == 0 ? Wk : (head == 1 ? Wq : Wv));
    float4 v = src[off];
    uint4 u;
    u.x = f2tf32(v.x); u.y = f2tf32(v.y); u.z = f2tf32(v.z); u.w = f2tf32(v.w);
    ((uint4*)g_wt)[f] = u;
}

// =================================================================
// Kernel 1: fused QKV projection via mma.sync tf32 (unchanged).
// =================================================================
#define PXS 68
#define PROJ_STAGE ((128 + 192) * PXS)
#define PROJ_SMEM  (PROJ_STAGE * 2 * 4)

__global__ void __launch_bounds__(256, 1) proj_mma(const float* __restrict__ x)
{
    extern __shared__ u32 psm[];

    const int tid  = threadIdx.x;
    const int w    = tid >> 5;
    const int lane = tid & 31;
    const int lq   = lane >> 2;
    const int lk   = lane & 3;
    const int wrow = w >> 1;
    const int wcol = w & 1;
    const int m0   = blockIdx.x * 128;

    float acc[2][12][4];
#pragma unroll
    for (int mi = 0; mi < 2; mi++)
#pragma unroll
        for (int nt = 0; nt < 12; nt++)
#pragma unroll
            for (int e = 0; e < 4; e++) acc[mi][nt][e] = 0.0f;

    const u32* wt = (const u32*)g_wt;

#define PROJ_FILL(SB, CH) do {                                               \
    u32* xs_ = (SB);                                                         \
    u32  wsa_ = smem_u32((SB) + 128 * PXS);                                  \
    _Pragma("unroll")                                                        \
    for (int i_ = 0; i_ < 12; i_++) {                                        \
        int idx_ = tid + i_ * 256;                                           \
        int r_ = idx_ >> 4, c4_ = idx_ & 15;                                 \
        CP16(wsa_ + (u32)(r_ * PXS + c4_ * 4) * 4,                           \
             (const void*)(wt + (size_t)r_ * C_ + (CH) * 64 + c4_ * 4));     \
    }                                                                        \
    _Pragma("unroll")                                                        \
    for (int i_ = 0; i_ < 8; i_++) {                                         \
        int idx_ = tid + i_ * 256;                                           \
        int r_ = idx_ >> 4, c4_ = idx_ & 15;                                 \
        float4 v_ = *(const float4*)(x + (size_t)(m0 + r_) * C_ + (CH) * 64 + c4_ * 4); \
        uint4 u_;                                                            \
        u_.x = f2tf32(v_.x); u_.y = f2tf32(v_.y);                            \
        u_.z = f2tf32(v_.z); u_.w = f2tf32(v_.w);                            \
        *(uint4*)(xs_ + r_ * PXS + c4_ * 4) = u_;                            \
    }                                                                        \
    CP_COMMIT();                                                             \
} while (0)

    PROJ_FILL(psm, 0);
    CP_WAIT0();
    __syncthreads();

    for (int ch = 0; ch < 16; ch++) {
        const int cur = ch & 1;
        if (ch + 1 < 16) {
            u32* nb = psm + ((ch + 1) & 1) * PROJ_STAGE;
            PROJ_FILL(nb, ch + 1);
        }
        {
            u32* sb = psm + cur * PROJ_STAGE;
            const u32* xbase = sb + (wrow * 32 + lq) * PXS + lk;
            const u32* wbase = sb + 128 * PXS + (wcol * 96 + lq) * PXS + lk;
#pragma unroll
            for (int ks = 0; ks < 8; ks++) {
                u32 a[2][4];
#pragma unroll
                for (int mi = 0; mi < 2; mi++) {
                    a[mi][0] = xbase[(mi * 16    ) * PXS + ks * 8];
                    a[mi][1] = xbase[(mi * 16 + 8) * PXS + ks * 8];
                    a[mi][2] = xbase[(mi * 16    ) * PXS + ks * 8 + 4];
                    a[mi][3] = xbase[(mi * 16 + 8) * PXS + ks * 8 + 4];
                }
#pragma unroll
                for (int nt = 0; nt < 12; nt++) {
                    u32 b0 = wbase[nt * 8 * PXS + ks * 8];
                    u32 b1 = wbase[nt * 8 * PXS + ks * 8 + 4];
                    mma_tf32(acc[0][nt][0], acc[0][nt][1], acc[0][nt][2], acc[0][nt][3],
                             a[0][0], a[0][1], a[0][2], a[0][3], b0, b1);
                    mma_tf32(acc[1][nt][0], acc[1][nt][1], acc[1][nt][2], acc[1][nt][3],
                             a[1][0], a[1][1], a[1][2], a[1][3], b0, b1);
                }
            }
        }
        if (ch + 1 < 16) CP_WAIT0();
        __syncthreads();
    }

#pragma unroll
    for (int mi = 0; mi < 2; mi++) {
#pragma unroll
        for (int nt = 0; nt < 12; nt++) {
            int gr = m0 + wrow * 32 + mi * 16 + lq;
            int gh = wcol * 96 + nt * 8 + 2 * lk;
            int head = gh >> 6;
            int hc   = gh & 63;
            float* op = (head == 0) ? g_k : ((head == 1) ? g_q : g_v);
            float v0 = __uint_as_float(f2tf32(acc[mi][nt][0]));
            float v1 = __uint_as_float(f2tf32(acc[mi][nt][1]));
            float v2 = __uint_as_float(f2tf32(acc[mi][nt][2]));
            float v3 = __uint_as_float(f2tf32(acc[mi][nt][3]));
            *(float2*)(op + (size_t)gr * H_ + hc)       = make_float2(v0, v1);
            *(float2*)(op + (size_t)(gr + 8) * H_ + hc) = make_float2(v2, v3);
        }
    }
}

// =================================================================
// Kernel 2: attention, 4-way split-K, 64-key tiles, double-buffered
//   cp.async pipeline. 512 CTAs: (b, mblk, quarter). Heavy first.
// =================================================================
#define KTILE 64
#define KSTR 76
#define VSTR 72
#define STG_WORDS (KTILE * (KSTR + VSTR))       // 9472 words / stage
#define ATTN_SMEM (STG_WORDS * 2 * 4)           // 75776 B -> occ 2
#define SCEXP (1.0f / 64.0f)

__global__ void __launch_bounds__(256, 2) attn_mma(int dummy)
{
    extern __shared__ u32 smw[];
    const u32 smb = smem_u32(smw);

    const int tid  = threadIdx.x;
    const int w    = tid >> 5;
    const int lane = tid & 31;
    const int lq   = lane >> 2;
    const int lk   = lane & 3;

    const int part = blockIdx.x & 3;
    const int pid  = blockIdx.x >> 2;
    const int b    = pid & 3;
    const int mblk = 31 - (pid >> 2);      // heavy first
    const int m0   = mblk * 128;

    const int nkt = min(2 * mblk + 3, T_ / KTILE);
    const int t_beg = (nkt * part) >> 2;
    const int t_end = (nkt * (part + 1)) >> 2;

    const int qa = m0 + w * 16 + lq;
    const int qb = qa + 8;
    const int qwmax = m0 + w * 16 + 15;

    // ---- Q fragments (raw bits — pre-rounded tf32) ----
    u32 qf[8][4];
    {
        const u32* qp = (const u32*)(g_q + ((size_t)b * T_ + qa) * H_) + lk;
#pragma unroll
        for (int ks = 0; ks < 8; ks++) {
            qf[ks][0] = qp[ks * 8];
            qf[ks][1] = qp[8 * H_ + ks * 8];
            qf[ks][2] = qp[ks * 8 + 4];
            qf[ks][3] = qp[8 * H_ + ks * 8 + 4];
        }
    }

    float oc[8][4];
#pragma unroll
    for (int i = 0; i < 8; i++)
#pragma unroll
        for (int j = 0; j < 4; j++) oc[i][j] = 0.0f;
    float ls_a = 0.0f, ls_b = 0.0f;

    // fill of tile T into stage STG (8 cp.async/thread, one group)
#define ATTN_FILL(STG, T) do {                                               \
    const float4* kg_ = (const float4*)(g_k + ((size_t)b * T_ + (size_t)(T) * KTILE) * H_); \
    const float4* vg_ = (const float4*)(g_v + ((size_t)b * T_ + (size_t)(T) * KTILE) * H_); \
    u32 base_ = smb + (u32)(STG) * (STG_WORDS * 4);                          \
    _Pragma("unroll")                                                        \
    for (int i_ = 0; i_ < 4; i_++) {                                         \
        int idx_ = tid + i_ * 256;                                           \
        int key_ = idx_ >> 4, c4_ = idx_ & 15;                               \
        CP16(base_ + (u32)(key_ * KSTR + c4_ * 4) * 4,                       \
             (const void*)(kg_ + (size_t)key_ * 16 + c4_));                  \
        CP16(base_ + (u32)(KTILE * KSTR + key_ * VSTR + c4_ * 4) * 4,        \
             (const void*)(vg_ + (size_t)key_ * 16 + c4_));                  \
    }                                                                        \
    CP_COMMIT();                                                             \
} while (0)

    if (t_beg < t_end) ATTN_FILL(t_beg & 1, t_beg);

    for (int t = t_beg; t < t_end; t++) {
        const int j0 = t * KTILE;
        const bool pre = (t + 1 < t_end);
        if (pre) {
            ATTN_FILL((t + 1) & 1, t + 1);
            CP_WAIT1();
        } else {
            CP_WAIT0();
        }
        __syncthreads();

        const u32* smK = smw + (t & 1) * STG_WORDS;
        const u32* smV = smK + KTILE * KSTR;

        const int ntmax = min((KTILE / 8) - 1, (qwmax + 1 - j0) >> 3);
        for (int nt = 0; nt <= ntmax; nt++) {
            // ---- S frag: two independent 4-step chains ----
            float s0 = 0, s1 = 0, s2 = 0, s3 = 0;
            float u0 = 0, u1 = 0, u2 = 0, u3 = 0;
            const u32* kb = smK + (nt * 8 + lq) * KSTR + lk;
#pragma unroll
            for (int ks = 0; ks < 4; ks++) {
                u32 b0 = kb[ks * 8];
                u32 b1 = kb[ks * 8 + 4];
                mma_tf32(s0, s1, s2, s3, qf[ks][0], qf[ks][1], qf[ks][2], qf[ks][3], b0, b1);
            }
#pragma unroll
            for (int ks = 4; ks < 8; ks++) {
                u32 b0 = kb[ks * 8];
                u32 b1 = kb[ks * 8 + 4];
                mma_tf32(u0, u1, u2, u3, qf[ks][0], qf[ks][1], qf[ks][2], qf[ks][3], b0, b1);
            }
            s0 += u0; s1 += u1; s2 += u2; s3 += u3;

            // ---- mask + exp + lsum ----
            const int jb = j0 + nt * 8 + 2 * lk;
            float p0 = (jb     <= qa + 1) ? __expf(s0 * SCEXP) : 0.0f;
            float p1 = (jb + 1 <= qa + 1) ? __expf(s1 * SCEXP) : 0.0f;
            float p2 = (jb     <= qb + 1) ? __expf(s2 * SCEXP) : 0.0f;
            float p3 = (jb + 1 <= qb + 1) ? __expf(s3 * SCEXP) : 0.0f;
            ls_a += p0 + p1;
            ls_b += p2 + p3;

            u32 sc0 = f2tf32(p0), sc1 = f2tf32(p1);
            u32 sc2 = f2tf32(p2), sc3 = f2tf32(p3);

            // ---- C-frag -> A-frag permutation ----
            const int src  = (lane & ~3) | (lk >> 1);
            const int src2 = src + 2;
            u32 t0a = __shfl_sync(0xffffffffu, sc0, src);
            u32 t1a = __shfl_sync(0xffffffffu, sc1, src);
            u32 t2a = __shfl_sync(0xffffffffu, sc2, src);
            u32 t3a = __shfl_sync(0xffffffffu, sc3, src);
            u32 t0b = __shfl_sync(0xffffffffu, sc0, src2);
            u32 t1b = __shfl_sync(0xffffffffu, sc1, src2);
            u32 t2b = __shfl_sync(0xffffffffu, sc2, src2);
            u32 t3b = __shfl_sync(0xffffffffu, sc3, src2);
            const bool odd = (lane & 1);
            u32 pa0 = odd ? t1a : t0a;
            u32 pa1 = odd ? t3a : t2a;
            u32 pa2 = odd ? t1b : t0b;
            u32 pa3 = odd ? t3b : t2b;

            // ---- O += P V ----
            const u32* vb = smV + (nt * 8 + lk) * VSTR + lq;
#pragma unroll
            for (int ot = 0; ot < 8; ot++) {
                u32 b0 = vb[ot * 8];
                u32 b1 = vb[4 * VSTR + ot * 8];
                mma_tf32(oc[ot][0], oc[ot][1], oc[ot][2], oc[ot][3],
                         pa0, pa1, pa2, pa3, b0, b1);
            }
        }
        __syncthreads();
    }

    // ---- write partial lsum (quad reduce); zeros if no tiles ----
    ls_a += __shfl_xor_sync(0xffffffffu, ls_a, 1);
    ls_a += __shfl_xor_sync(0xffffffffu, ls_a, 2);
    ls_b += __shfl_xor_sync(0xffffffffu, ls_b, 1);
    ls_b += __shfl_xor_sync(0xffffffffu, ls_b, 2);
    float* lp = g_l[part];
    if (lk == 0) {
        lp[(size_t)b * T_ + qa] = ls_a;
        lp[(size_t)b * T_ + qb] = ls_b;
    }

    // ---- write partial O (zeros if no tiles) ----
    float* pp = g_p[part];
    float* ra = pp + ((size_t)b * T_ + qa) * H_ + 2 * lk;
    float* rb = pp + ((size_t)b * T_ + qb) * H_ + 2 * lk;
#pragma unroll
    for (int ot = 0; ot < 8; ot++) {
        *(float2*)(ra + ot * 8) = make_float2(oc[ot][0], oc[ot][1]);
        *(float2*)(rb + ot * 8) = make_float2(oc[ot][2], oc[ot][3]);
    }
    (void)dummy;
}

// =================================================================
// Kernel 3: combine 4 quarters + normalize.
// =================================================================
__global__ void __launch_bounds__(256) norm_out(float* __restrict__ out)
{
    int i4 = blockIdx.x * 256 + threadIdx.x;
    int row = i4 >> 4;
    float inv = 1.0f / (g_l[0][row] + g_l[1][row] + g_l[2][row] + g_l[3][row]);
    float4 a = ((const float4*)g_p[0])[i4];
    float4 c = ((const float4*)g_p[1])[i4];
    float4 d = ((const float4*)g_p[2])[i4];
    float4 e = ((const float4*)g_p[3])[i4];
    float4 o;
    o.x = (a.x + c.x + d.x + e.x) * inv;
    o.y = (a.y + c.y + d.y + e.y) * inv;
    o.z = (a.z + c.z + d.z + e.z) * inv;
    o.w = (a.w + c.w + d.w + e.w) * inv;
    ((float4*)out)[i4] = o;
}

// =================================================================
// launch
// =================================================================
extern "C" void kernel_launch(void* const* d_in, const int* in_sizes, int n_in,
                              void* d_out, int out_size)
{
    const float* x  = (const float*)d_in[0];
    const float* Wk = (const float*)d_in[1];
    const float* Wq = (const float*)d_in[2];
    const float* Wv = (const float*)d_in[3];
    float* out = (float*)d_out;

    (void)in_sizes; (void)n_in; (void)out_size;

    cudaFuncSetAttribute(proj_mma, cudaFuncAttributeMaxDynamicSharedMemorySize, PROJ_SMEM);
    cudaFuncSetAttribute(attn_mma, cudaFuncAttributeMaxDynamicSharedMemorySize, ATTN_SMEM);

    w_cvt<<<192, 256>>>(Wk, Wq, Wv);
    proj_mma<<<BT_ / 128, 256, PROJ_SMEM>>>(x);
    attn_mma<<<512, 256, ATTN_SMEM>>>(0);
    norm_out<<<(BT_ * H_ / 4) / 256, 256>>>(out);
}

// round 7
// speedup vs baseline: 3.5495x; 1.0377x over previous
#include <cuda_runtime.h>
#include <cstdint>

// Problem constants
#define B_  4
#define T_  4096
#define C_  1024
#define H_  64
#define BT_ (B_*T_)

typedef unsigned long long u64;
typedef unsigned int u32;

// Scratch — device globals, no allocation.
__device__ float g_k[(size_t)BT_ * H_];
__device__ float g_q[(size_t)BT_ * H_];
__device__ float g_v[(size_t)BT_ * H_];
__device__ float g_wt[192 * C_];            // pre-tf32-rounded W (k|q|v rows)
__device__ float g_p[4][(size_t)BT_ * H_];  // partial O per key-quarter
__device__ float g_l[4][(size_t)BT_];       // partial lsum per key-quarter

// ---------------- helpers ----------------
__device__ __forceinline__ u32 f2tf32(float f) {
    u32 u; asm("cvt.rna.tf32.f32 %0, %1;" : "=r"(u) : "f"(f)); return u;
}
__device__ __forceinline__ void mma_tf32(
    float& d0, float& d1, float& d2, float& d3,
    u32 a0, u32 a1, u32 a2, u32 a3, u32 b0, u32 b1)
{
    asm volatile(
        "mma.sync.aligned.m16n8k8.row.col.f32.tf32.tf32.f32 "
        "{%0,%1,%2,%3}, {%4,%5,%6,%7}, {%8,%9}, {%0,%1,%2,%3};"
        : "+f"(d0), "+f"(d1), "+f"(d2), "+f"(d3)
        : "r"(a0), "r"(a1), "r"(a2), "r"(a3), "r"(b0), "r"(b1));
}
__device__ __forceinline__ u32 smem_u32(const void* p) {
    u32 a;
    asm("{ .reg .u64 t; cvta.to.shared.u64 t, %1; cvt.u32.u64 %0, t; }" : "=r"(a) : "l"(p));
    return a;
}
#define CP16(dst, src) asm volatile("cp.async.ca.shared.global [%0], [%1], 16;" :: "r"(dst), "l"(src) : "memory")
#define CP_COMMIT()    asm volatile("cp.async.commit_group;" ::: "memory")
#define CP_WAIT0()     asm volatile("cp.async.wait_group 0;" ::: "memory")
#define CP_WAIT1()     asm volatile("cp.async.wait_group 1;" ::: "memory")

// =================================================================
// Kernel 0: pre-round W (Wk|Wq|Wv) to tf32, store concatenated.
// =================================================================
__global__ void __launch_bounds__(256) w_cvt(
    const float* __restrict__ Wk, const float* __restrict__ Wq,
    const float* __restrict__ Wv)
{
    int f = blockIdx.x * 256 + threadIdx.x;
    int head = f >> 14;
    int off  = f & 16383;
    const float4* src = (const float4*)(head == 0 ? Wk : (head == 1 ? Wq : Wv));
    float4 v = src[off];
    uint4 u;
    u.x = f2tf32(v.x); u.y = f2tf32(v.y); u.z = f2tf32(v.z); u.w = f2tf32(v.w);
    ((uint4*)g_wt)[f] = u;
}

// =================================================================
// Kernel 1: fused QKV projection via mma.sync tf32 (unchanged).
// =================================================================
#define PXS 68
#define PROJ_STAGE ((128 + 192) * PXS)
#define PROJ_SMEM  (PROJ_STAGE * 2 * 4)

__global__ void __launch_bounds__(256, 1) proj_mma(const float* __restrict__ x)
{
    extern __shared__ u32 psm[];

    const int tid  = threadIdx.x;
    const int w    = tid >> 5;
    const int lane = tid & 31;
    const int lq   = lane >> 2;
    const int lk   = lane & 3;
    const int wrow = w >> 1;
    const int wcol = w & 1;
    const int m0   = blockIdx.x * 128;

    float acc[2][12][4];
#pragma unroll
    for (int mi = 0; mi < 2; mi++)
#pragma unroll
        for (int nt = 0; nt < 12; nt++)
#pragma unroll
            for (int e = 0; e < 4; e++) acc[mi][nt][e] = 0.0f;

    const u32* wt = (const u32*)g_wt;

#define PROJ_FILL(SB, CH) do {                                               \
    u32* xs_ = (SB);                                                         \
    u32  wsa_ = smem_u32((SB) + 128 * PXS);                                  \
    _Pragma("unroll")                                                        \
    for (int i_ = 0; i_ < 12; i_++) {                                        \
        int idx_ = tid + i_ * 256;                                           \
        int r_ = idx_ >> 4, c4_ = idx_ & 15;                                 \
        CP16(wsa_ + (u32)(r_ * PXS + c4_ * 4) * 4,                           \
             (const void*)(wt + (size_t)r_ * C_ + (CH) * 64 + c4_ * 4));     \
    }                                                                        \
    _Pragma("unroll")                                                        \
    for (int i_ = 0; i_ < 8; i_++) {                                         \
        int idx_ = tid + i_ * 256;                                           \
        int r_ = idx_ >> 4, c4_ = idx_ & 15;                                 \
        float4 v_ = *(const float4*)(x + (size_t)(m0 + r_) * C_ + (CH) * 64 + c4_ * 4); \
        uint4 u_;                                                            \
        u_.x = f2tf32(v_.x); u_.y = f2tf32(v_.y);                            \
        u_.z = f2tf32(v_.z); u_.w = f2tf32(v_.w);                            \
        *(uint4*)(xs_ + r_ * PXS + c4_ * 4) = u_;                            \
    }                                                                        \
    CP_COMMIT();                                                             \
} while (0)

    PROJ_FILL(psm, 0);
    CP_WAIT0();
    __syncthreads();

    for (int ch = 0; ch < 16; ch++) {
        const int cur = ch & 1;
        if (ch + 1 < 16) {
            u32* nb = psm + ((ch + 1) & 1) * PROJ_STAGE;
            PROJ_FILL(nb, ch + 1);
        }
        {
            u32* sb = psm + cur * PROJ_STAGE;
            const u32* xbase = sb + (wrow * 32 + lq) * PXS + lk;
            const u32* wbase = sb + 128 * PXS + (wcol * 96 + lq) * PXS + lk;
#pragma unroll
            for (int ks = 0; ks < 8; ks++) {
                u32 a[2][4];
#pragma unroll
                for (int mi = 0; mi < 2; mi++) {
                    a[mi][0] = xbase[(mi * 16    ) * PXS + ks * 8];
                    a[mi][1] = xbase[(mi * 16 + 8) * PXS + ks * 8];
                    a[mi][2] = xbase[(mi * 16    ) * PXS + ks * 8 + 4];
                    a[mi][3] = xbase[(mi * 16 + 8) * PXS + ks * 8 + 4];
                }
#pragma unroll
                for (int nt = 0; nt < 12; nt++) {
                    u32 b0 = wbase[nt * 8 * PXS + ks * 8];
                    u32 b1 = wbase[nt * 8 * PXS + ks * 8 + 4];
                    mma_tf32(acc[0][nt][0], acc[0][nt][1], acc[0][nt][2], acc[0][nt][3],
                             a[0][0], a[0][1], a[0][2], a[0][3], b0, b1);
                    mma_tf32(acc[1][nt][0], acc[1][nt][1], acc[1][nt][2], acc[1][nt][3],
                             a[1][0], a[1][1], a[1][2], a[1][3], b0, b1);
                }
            }
        }
        if (ch + 1 < 16) CP_WAIT0();
        __syncthreads();
    }

#pragma unroll
    for (int mi = 0; mi < 2; mi++) {
#pragma unroll
        for (int nt = 0; nt < 12; nt++) {
            int gr = m0 + wrow * 32 + mi * 16 + lq;
            int gh = wcol * 96 + nt * 8 + 2 * lk;
            int head = gh >> 6;
            int hc   = gh & 63;
            float* op = (head == 0) ? g_k : ((head == 1) ? g_q : g_v);
            float v0 = __uint_as_float(f2tf32(acc[mi][nt][0]));
            float v1 = __uint_as_float(f2tf32(acc[mi][nt][1]));
            float v2 = __uint_as_float(f2tf32(acc[mi][nt][2]));
            float v3 = __uint_as_float(f2tf32(acc[mi][nt][3]));
            *(float2*)(op + (size_t)gr * H_ + hc)       = make_float2(v0, v1);
            *(float2*)(op + (size_t)(gr + 8) * H_ + hc) = make_float2(v2, v3);
        }
    }
}

// =================================================================
// Kernel 2: attention. 128-thread CTAs, 4 warps x 32 q-rows each
//   (B-fragments amortized over 2x M). 4-way split-K, 64-key tiles,
//   double-buffered cp.async. 512 CTAs: (b, mblk, quarter).
// =================================================================
#define KTILE 64
#define KSTR 76
#define VSTR 72
#define STG_WORDS (KTILE * (KSTR + VSTR))       // 9472 words / stage
#define ATTN_SMEM (STG_WORDS * 2 * 4)           // 75776 B
#define SCEXP (1.0f / 64.0f)

__global__ void __launch_bounds__(128, 2) attn_mma(int dummy)
{
    extern __shared__ u32 smw[];
    const u32 smb = smem_u32(smw);

    const int tid  = threadIdx.x;
    const int w    = tid >> 5;         // 0..3
    const int lane = tid & 31;
    const int lq   = lane >> 2;
    const int lk   = lane & 3;

    const int part = blockIdx.x & 3;
    const int pid  = blockIdx.x >> 2;
    const int b    = pid & 3;
    const int mblk = 31 - (pid >> 2);      // heavy first
    const int m0   = mblk * 128;

    const int nkt = min(2 * mblk + 3, T_ / KTILE);
    const int t_beg = (nkt * part) >> 2;
    const int t_end = (nkt * (part + 1)) >> 2;

    const int qbase = m0 + w * 32;         // warp's 32 query rows
    const int qa0   = qbase + lq;          // thread's 4 row-ids
    // mi=0: rows qa0, qa0+8 ; mi=1: rows qa0+16, qa0+24

    // ---- Q fragments for both 16-row halves (raw tf32 bits) ----
    u32 qf[2][8][4];
#pragma unroll
    for (int mi = 0; mi < 2; mi++) {
        const u32* qp = (const u32*)(g_q + ((size_t)b * T_ + qa0 + mi * 16) * H_) + lk;
#pragma unroll
        for (int ks = 0; ks < 8; ks++) {
            qf[mi][ks][0] = qp[ks * 8];
            qf[mi][ks][1] = qp[8 * H_ + ks * 8];
            qf[mi][ks][2] = qp[ks * 8 + 4];
            qf[mi][ks][3] = qp[8 * H_ + ks * 8 + 4];
        }
    }

    float oc[2][8][4];
#pragma unroll
    for (int mi = 0; mi < 2; mi++)
#pragma unroll
        for (int i = 0; i < 8; i++)
#pragma unroll
            for (int j = 0; j < 4; j++) oc[mi][i][j] = 0.0f;
    float ls[4] = {0.0f, 0.0f, 0.0f, 0.0f};

    // fill of tile T into stage STG (16 cp.async/thread, one group)
#define ATTN_FILL(STG, T) do {                                               \
    const float4* kg_ = (const float4*)(g_k + ((size_t)b * T_ + (size_t)(T) * KTILE) * H_); \
    const float4* vg_ = (const float4*)(g_v + ((size_t)b * T_ + (size_t)(T) * KTILE) * H_); \
    u32 base_ = smb + (u32)(STG) * (STG_WORDS * 4);                          \
    _Pragma("unroll")                                                        \
    for (int i_ = 0; i_ < 8; i_++) {                                         \
        int idx_ = tid + i_ * 128;                                           \
        int key_ = idx_ >> 4, c4_ = idx_ & 15;                               \
        CP16(base_ + (u32)(key_ * KSTR + c4_ * 4) * 4,                       \
             (const void*)(kg_ + (size_t)key_ * 16 + c4_));                  \
        CP16(base_ + (u32)(KTILE * KSTR + key_ * VSTR + c4_ * 4) * 4,        \
             (const void*)(vg_ + (size_t)key_ * 16 + c4_));                  \
    }                                                                        \
    CP_COMMIT();                                                             \
} while (0)

    if (t_beg < t_end) ATTN_FILL(t_beg & 1, t_beg);

    for (int t = t_beg; t < t_end; t++) {
        const int j0 = t * KTILE;
        const bool pre = (t + 1 < t_end);
        if (pre) {
            ATTN_FILL((t + 1) & 1, t + 1);
            CP_WAIT1();
        } else {
            CP_WAIT0();
        }
        __syncthreads();

        const u32* smK = smw + (t & 1) * STG_WORDS;
        const u32* smV = smK + KTILE * KSTR;

        const int ntmax = min((KTILE / 8) - 1, (qbase + 32 - j0) >> 3);
        for (int nt = 0; nt <= ntmax; nt++) {
            // ---- S frags for both halves (two independent chains) ----
            float s[2][4] = {{0, 0, 0, 0}, {0, 0, 0, 0}};
            const u32* kb = smK + (nt * 8 + lq) * KSTR + lk;
#pragma unroll
            for (int ks = 0; ks < 8; ks++) {
                u32 b0 = kb[ks * 8];
                u32 b1 = kb[ks * 8 + 4];
                mma_tf32(s[0][0], s[0][1], s[0][2], s[0][3],
                         qf[0][ks][0], qf[0][ks][1], qf[0][ks][2], qf[0][ks][3], b0, b1);
                mma_tf32(s[1][0], s[1][1], s[1][2], s[1][3],
                         qf[1][ks][0], qf[1][ks][1], qf[1][ks][2], qf[1][ks][3], b0, b1);
            }

            // ---- mask + exp + lsum + tf32 round ----
            const int jb = j0 + nt * 8 + 2 * lk;
            u32 sc[2][4];
#pragma unroll
            for (int mi = 0; mi < 2; mi++) {
                const int ra = qa0 + mi * 16;
                const int rb = ra + 8;
                float p0 = (jb     <= ra + 1) ? __expf(s[mi][0] * SCEXP) : 0.0f;
                float p1 = (jb + 1 <= ra + 1) ? __expf(s[mi][1] * SCEXP) : 0.0f;
                float p2 = (jb     <= rb + 1) ? __expf(s[mi][2] * SCEXP) : 0.0f;
                float p3 = (jb + 1 <= rb + 1) ? __expf(s[mi][3] * SCEXP) : 0.0f;
                ls[mi * 2]     += p0 + p1;
                ls[mi * 2 + 1] += p2 + p3;
                sc[mi][0] = f2tf32(p0); sc[mi][1] = f2tf32(p1);
                sc[mi][2] = f2tf32(p2); sc[mi][3] = f2tf32(p3);
            }

            // ---- C-frag -> A-frag permutation (both halves) ----
            const int src  = (lane & ~3) | (lk >> 1);
            const int src2 = src + 2;
            const bool odd = (lane & 1);
            u32 pa[2][4];
#pragma unroll
            for (int mi = 0; mi < 2; mi++) {
                u32 t0a = __shfl_sync(0xffffffffu, sc[mi][0], src);
                u32 t1a = __shfl_sync(0xffffffffu, sc[mi][1], src);
                u32 t2a = __shfl_sync(0xffffffffu, sc[mi][2], src);
                u32 t3a = __shfl_sync(0xffffffffu, sc[mi][3], src);
                u32 t0b = __shfl_sync(0xffffffffu, sc[mi][0], src2);
                u32 t1b = __shfl_sync(0xffffffffu, sc[mi][1], src2);
                u32 t2b = __shfl_sync(0xffffffffu, sc[mi][2], src2);
                u32 t3b = __shfl_sync(0xffffffffu, sc[mi][3], src2);
                pa[mi][0] = odd ? t1a : t0a;
                pa[mi][1] = odd ? t3a : t2a;
                pa[mi][2] = odd ? t1b : t0b;
                pa[mi][3] = odd ? t3b : t2b;
            }

            // ---- O += P V (B-frags shared across both halves) ----
            const u32* vb = smV + (nt * 8 + lk) * VSTR + lq;
#pragma unroll
            for (int ot = 0; ot < 8; ot++) {
                u32 b0 = vb[ot * 8];
                u32 b1 = vb[4 * VSTR + ot * 8];
                mma_tf32(oc[0][ot][0], oc[0][ot][1], oc[0][ot][2], oc[0][ot][3],
                         pa[0][0], pa[0][1], pa[0][2], pa[0][3], b0, b1);
                mma_tf32(oc[1][ot][0], oc[1][ot][1], oc[1][ot][2], oc[1][ot][3],
                         pa[1][0], pa[1][1], pa[1][2], pa[1][3], b0, b1);
            }
        }
        __syncthreads();
    }

    // ---- write partial lsum (quad reduce); zeros if no tiles ----
#pragma unroll
    for (int i = 0; i < 4; i++) {
        ls[i] += __shfl_xor_sync(0xffffffffu, ls[i], 1);
        ls[i] += __shfl_xor_sync(0xffffffffu, ls[i], 2);
    }
    float* lp = g_l[part];
    if (lk == 0) {
        lp[(size_t)b * T_ + qa0]      = ls[0];
        lp[(size_t)b * T_ + qa0 + 8]  = ls[1];
        lp[(size_t)b * T_ + qa0 + 16] = ls[2];
        lp[(size_t)b * T_ + qa0 + 24] = ls[3];
    }

    // ---- write partial O (zeros if no tiles) ----
    float* pp = g_p[part];
#pragma unroll
    for (int mi = 0; mi < 2; mi++) {
        float* ra = pp + ((size_t)b * T_ + qa0 + mi * 16) * H_ + 2 * lk;
        float* rb = ra + (size_t)8 * H_;
#pragma unroll
        for (int ot = 0; ot < 8; ot++) {
            *(float2*)(ra + ot * 8) = make_float2(oc[mi][ot][0], oc[mi][ot][1]);
            *(float2*)(rb + ot * 8) = make_float2(oc[mi][ot][2], oc[mi][ot][3]);
        }
    }
    (void)dummy;
}

// =================================================================
// Kernel 3: combine 4 quarters + normalize.
// =================================================================
__global__ void __launch_bounds__(256) norm_out(float* __restrict__ out)
{
    int i4 = blockIdx.x * 256 + threadIdx.x;
    int row = i4 >> 4;
    float inv = 1.0f / (g_l[0][row] + g_l[1][row] + g_l[2][row] + g_l[3][row]);
    float4 a = ((const float4*)g_p[0])[i4];
    float4 c = ((const float4*)g_p[1])[i4];
    float4 d = ((const float4*)g_p[2])[i4];
    float4 e = ((const float4*)g_p[3])[i4];
    float4 o;
    o.x = (a.x + c.x + d.x + e.x) * inv;
    o.y = (a.y + c.y + d.y + e.y) * inv;
    o.z = (a.z + c.z + d.z + e.z) * inv;
    o.w = (a.w + c.w + d.w + e.w) * inv;
    ((float4*)out)[i4] = o;
}

// =================================================================
// launch
// =================================================================
extern "C" void kernel_launch(void* const* d_in, const int* in_sizes, int n_in,
                              void* d_out, int out_size)
{
    const float* x  = (const float*)d_in[0];
    const float* Wk = (const float*)d_in[1];
    const float* Wq = (const float*)d_in[2];
    const float* Wv = (const float*)d_in[3];
    float* out = (float*)d_out;

    (void)in_sizes; (void)n_in; (void)out_size;

    cudaFuncSetAttribute(proj_mma, cudaFuncAttributeMaxDynamicSharedMemorySize, PROJ_SMEM);
    cudaFuncSetAttribute(attn_mma, cudaFuncAttributeMaxDynamicSharedMemorySize, ATTN_SMEM);

    w_cvt<<<192, 256>>>(Wk, Wq, Wv);
    proj_mma<<<BT_ / 128, 256, PROJ_SMEM>>>(x);
    attn_mma<<<512, 128, ATTN_SMEM>>>(0);
    norm_out<<<(BT_ * H_ / 4) / 256, 256>>>(out);
}

// round 8
// speedup vs baseline: 5.2736x; 1.4857x over previous
#include <cuda_runtime.h>
#include <cuda_fp16.h>
#include <cstdint>

// Problem constants
#define B_  4
#define T_  4096
#define C_  1024
#define H_  64
#define BT_ (B_*T_)

typedef unsigned long long u64;
typedef unsigned int u32;

// Scratch — device globals, no allocation.
__device__ __half g_kh[(size_t)BT_ * H_];   // k, fp16 [b][t][h]
__device__ __half g_qh[(size_t)BT_ * H_];   // q, fp16 [b][t][h]
__device__ __half g_vt[(size_t)H_ * BT_];   // v^T, fp16 [h][b*T+t]
__device__ __half g_wh[192 * C_];           // fp16 W (k|q|v rows)
__device__ float  g_p[4][(size_t)BT_ * H_]; // partial O per key-quarter
__device__ float  g_l[4][(size_t)BT_];      // partial lsum per key-quarter

// ---------------- helpers ----------------
__device__ __forceinline__ u32 pack16(float hi, float lo) {
    u32 d; asm("cvt.rn.f16x2.f32 %0, %1, %2;" : "=r"(d) : "f"(hi), "f"(lo)); return d;
}
__device__ __forceinline__ void mma_f16(
    float& d0, float& d1, float& d2, float& d3,
    u32 a0, u32 a1, u32 a2, u32 a3, u32 b0, u32 b1)
{
    asm volatile(
        "mma.sync.aligned.m16n8k16.row.col.f32.f16.f16.f32 "
        "{%0,%1,%2,%3}, {%4,%5,%6,%7}, {%8,%9}, {%0,%1,%2,%3};"
        : "+f"(d0), "+f"(d1), "+f"(d2), "+f"(d3)
        : "r"(a0), "r"(a1), "r"(a2), "r"(a3), "r"(b0), "r"(b1));
}
__device__ __forceinline__ u32 smem_u32(const void* p) {
    u32 a;
    asm("{ .reg .u64 t; cvta.to.shared.u64 t, %1; cvt.u32.u64 %0, t; }" : "=r"(a) : "l"(p));
    return a;
}
#define CP16(dst, src) asm volatile("cp.async.ca.shared.global [%0], [%1], 16;" :: "r"(dst), "l"(src) : "memory")
#define CP_COMMIT()    asm volatile("cp.async.commit_group;" ::: "memory")
#define CP_WAIT0()     asm volatile("cp.async.wait_group 0;" ::: "memory")
#define CP_WAIT1()     asm volatile("cp.async.wait_group 1;" ::: "memory")

// =================================================================
// Kernel 0: convert W (Wk|Wq|Wv) to fp16, store concatenated.
// =================================================================
__global__ void __launch_bounds__(256) w_cvt(
    const float* __restrict__ Wk, const float* __restrict__ Wq,
    const float* __restrict__ Wv)
{
    int f = blockIdx.x * 256 + threadIdx.x;   // float4 index, 49152 total
    int head = f >> 14;
    int off  = f & 16383;
    const float4* src = (const float4*)(head == 0 ? Wk : (head == 1 ? Wq : Wv));
    float4 v = src[off];
    uint2 u;
    u.x = pack16(v.y, v.x);
    u.y = pack16(v.w, v.z);
    ((uint2*)g_wh)[f] = u;
}

// =================================================================
// Kernel 1: fused QKV projection via mma.sync fp16 (m16n8k16).
//   128 CTAs x (128 rows x 192 cols). 8 warps: (wrow 0..3) x (wcol 0..1).
//   BK=64 (4 k-steps of 16), double-buffered smem.
//   Outputs: g_kh/g_qh fp16 row-major, g_vt fp16 transposed.
// =================================================================
#define PST 36                                   // u32 stride per row (32 + 4 pad)
#define PROJ_STAGE ((128 + 192) * PST)           // words per stage
#define PROJ_SMEM  (PROJ_STAGE * 2 * 4)          // 92160 bytes

__global__ void __launch_bounds__(256, 1) proj_mma(const float* __restrict__ x)
{
    extern __shared__ u32 psm[];

    const int tid  = threadIdx.x;
    const int w    = tid >> 5;
    const int lane = tid & 31;
    const int lq   = lane >> 2;
    const int lk   = lane & 3;
    const int wrow = w >> 1;
    const int wcol = w & 1;
    const int m0   = blockIdx.x * 128;

    float acc[2][12][4];
#pragma unroll
    for (int mi = 0; mi < 2; mi++)
#pragma unroll
        for (int nt = 0; nt < 12; nt++)
#pragma unroll
            for (int e = 0; e < 4; e++) acc[mi][nt][e] = 0.0f;

#define PROJ_FILL(SB, CH) do {                                               \
    u32* xs_ = (SB);                                                         \
    u32  wsa_ = smem_u32((SB) + 128 * PST);                                  \
    _Pragma("unroll")                                                        \
    for (int i_ = 0; i_ < 6; i_++) {                                         \
        int idx_ = tid + i_ * 256;            /* 1536: 192 rows x 8 cp16 */  \
        int r_ = idx_ >> 3, c8_ = idx_ & 7;                                  \
        CP16(wsa_ + (u32)(r_ * PST + c8_ * 4) * 4,                           \
             (const void*)(g_wh + (size_t)r_ * C_ + (CH) * 64 + c8_ * 8));   \
    }                                                                        \
    _Pragma("unroll")                                                        \
    for (int i_ = 0; i_ < 8; i_++) {                                         \
        int idx_ = tid + i_ * 256;            /* 2048: 128 rows x 16 f4 */   \
        int r_ = idx_ >> 4, c4_ = idx_ & 15;                                 \
        float4 v_ = *(const float4*)(x + (size_t)(m0 + r_) * C_ + (CH) * 64 + c4_ * 4); \
        uint2 u_;                                                            \
        u_.x = pack16(v_.y, v_.x);                                           \
        u_.y = pack16(v_.w, v_.z);                                           \
        *(uint2*)(xs_ + r_ * PST + c4_ * 2) = u_;                            \
    }                                                                        \
    CP_COMMIT();                                                             \
} while (0)

    PROJ_FILL(psm, 0);
    CP_WAIT0();
    __syncthreads();

    for (int ch = 0; ch < 16; ch++) {
        const int cur = ch & 1;
        if (ch + 1 < 16) {
            u32* nb = psm + ((ch + 1) & 1) * PROJ_STAGE;
            PROJ_FILL(nb, ch + 1);
        }
        {
            u32* sb = psm + cur * PROJ_STAGE;
            const u32* xbase = sb + (wrow * 32 + lq) * PST + lk;
            const u32* wbase = sb + 128 * PST + (wcol * 96 + lq) * PST + lk;
#pragma unroll
            for (int ks = 0; ks < 4; ks++) {        // 16 dims per step
                u32 a[2][4];
#pragma unroll
                for (int mi = 0; mi < 2; mi++) {
                    a[mi][0] = xbase[(mi * 16    ) * PST + ks * 8];
                    a[mi][1] = xbase[(mi * 16 + 8) * PST + ks * 8];
                    a[mi][2] = xbase[(mi * 16    ) * PST + ks * 8 + 4];
                    a[mi][3] = xbase[(mi * 16 + 8) * PST + ks * 8 + 4];
                }
#pragma unroll
                for (int nt = 0; nt < 12; nt++) {
                    u32 b0 = wbase[nt * 8 * PST + ks * 8];
                    u32 b1 = wbase[nt * 8 * PST + ks * 8 + 4];
                    mma_f16(acc[0][nt][0], acc[0][nt][1], acc[0][nt][2], acc[0][nt][3],
                            a[0][0], a[0][1], a[0][2], a[0][3], b0, b1);
                    mma_f16(acc[1][nt][0], acc[1][nt][1], acc[1][nt][2], acc[1][nt][3],
                            a[1][0], a[1][1], a[1][2], a[1][3], b0, b1);
                }
            }
        }
        if (ch + 1 < 16) CP_WAIT0();
        __syncthreads();
    }

    // ---- epilogue: fp16 round; k/q row-major, v transposed ----
#pragma unroll
    for (int mi = 0; mi < 2; mi++) {
#pragma unroll
        for (int nt = 0; nt < 12; nt++) {
            int gr = m0 + wrow * 32 + mi * 16 + lq;
            int gh = wcol * 96 + nt * 8 + 2 * lk;
            int head = gh >> 6;
            int hc   = gh & 63;
            if (head < 2) {
                __half* op = head ? g_qh : g_kh;
                *(u32*)(op + (size_t)gr * H_ + hc)       = pack16(acc[mi][nt][1], acc[mi][nt][0]);
                *(u32*)(op + (size_t)(gr + 8) * H_ + hc) = pack16(acc[mi][nt][3], acc[mi][nt][2]);
            } else {
                g_vt[(size_t)hc * BT_ + gr]           = __float2half_rn(acc[mi][nt][0]);
                g_vt[(size_t)(hc + 1) * BT_ + gr]     = __float2half_rn(acc[mi][nt][1]);
                g_vt[(size_t)hc * BT_ + gr + 8]       = __float2half_rn(acc[mi][nt][2]);
                g_vt[(size_t)(hc + 1) * BT_ + gr + 8] = __float2half_rn(acc[mi][nt][3]);
            }
        }
    }
}

// =================================================================
// Kernel 2: attention via mma.sync fp16. 128-thread CTAs, 4 warps x
//   32 q-rows. 4-way split-K, 64-key tiles, double-buffered cp.async.
//   P C-frags pack directly into A-frags (no shuffles).
// =================================================================
#define KTILE 64
#define AST 36                                    // u32 row stride (32+4)
#define STG_WORDS (KTILE * AST * 2)               // K + V^T per stage
#define ATTN_SMEM (STG_WORDS * 2 * 4)             // 36864 B
#define SCEXP (1.0f / 64.0f)

__global__ void __launch_bounds__(128, 3) attn_mma(int dummy)
{
    extern __shared__ u32 smw[];
    const u32 smb = smem_u32(smw);

    const int tid  = threadIdx.x;
    const int w    = tid >> 5;         // 0..3
    const int lane = tid & 31;
    const int lq   = lane >> 2;
    const int lk   = lane & 3;

    const int part = blockIdx.x & 3;
    const int pid  = blockIdx.x >> 2;
    const int b    = pid & 3;
    const int mblk = 31 - (pid >> 2);      // heavy first
    const int m0   = mblk * 128;

    const int nkt = min(2 * mblk + 3, T_ / KTILE);
    const int t_beg = (nkt * part) >> 2;
    const int t_end = (nkt * (part + 1)) >> 2;

    const int qbase = m0 + w * 32;         // warp's 32 query rows
    const int qa0   = qbase + lq;

    // ---- Q A-frags fp16, 4 k-steps x 2 row-halves ----
    u32 qf[2][4][4];
#pragma unroll
    for (int mi = 0; mi < 2; mi++) {
        const u32* qp = (const u32*)(g_qh + ((size_t)b * T_ + qa0 + mi * 16) * H_) + lk;
#pragma unroll
        for (int ks = 0; ks < 4; ks++) {
            qf[mi][ks][0] = qp[ks * 8];
            qf[mi][ks][1] = qp[8 * 32 + ks * 8];
            qf[mi][ks][2] = qp[ks * 8 + 4];
            qf[mi][ks][3] = qp[8 * 32 + ks * 8 + 4];
        }
    }

    float oc[2][8][4];
#pragma unroll
    for (int mi = 0; mi < 2; mi++)
#pragma unroll
        for (int i = 0; i < 8; i++)
#pragma unroll
            for (int j = 0; j < 4; j++) oc[mi][i][j] = 0.0f;
    float ls[4] = {0.0f, 0.0f, 0.0f, 0.0f};

    // fill of tile T into stage STG: K rows + V^T rows, 8 cp16/thread
#define ATTN_FILL(STG, T) do {                                               \
    const __half* kg_ = g_kh + ((size_t)b * T_ + (size_t)(T) * KTILE) * H_;  \
    const __half* vg_ = g_vt + (size_t)b * T_ + (size_t)(T) * KTILE;         \
    u32 base_ = smb + (u32)(STG) * (STG_WORDS * 4);                          \
    _Pragma("unroll")                                                        \
    for (int i_ = 0; i_ < 4; i_++) {                                         \
        int idx_ = tid + i_ * 128;         /* 512: 64 rows x 8 cp16 */       \
        int r_ = idx_ >> 3, c8_ = idx_ & 7;                                  \
        CP16(base_ + (u32)(r_ * AST + c8_ * 4) * 4,                          \
             (const void*)(kg_ + (size_t)r_ * H_ + c8_ * 8));                \
        CP16(base_ + (u32)(KTILE * AST + r_ * AST + c8_ * 4) * 4,            \
             (const void*)(vg_ + (size_t)r_ * BT_ + c8_ * 8));               \
    }                                                                        \
    CP_COMMIT();                                                             \
} while (0)

    if (t_beg < t_end) ATTN_FILL(t_beg & 1, t_beg);

    for (int t = t_beg; t < t_end; t++) {
        const int j0 = t * KTILE;
        const bool pre = (t + 1 < t_end);
        if (pre) {
            ATTN_FILL((t + 1) & 1, t + 1);
            CP_WAIT1();
        } else {
            CP_WAIT0();
        }
        __syncthreads();

        const u32* smK = smw + (t & 1) * STG_WORDS;
        const u32* smV = smK + KTILE * AST;

        const int ktmax = min(3, (qbase + 32 - j0) >> 4);
        for (int kt = 0; kt <= ktmax; kt++) {
            // ---- S c-frags for 16 keys (2 groups of 8) x 2 row-halves ----
            float sg[2][2][4];
#pragma unroll
            for (int g = 0; g < 2; g++) {
                const u32* kb = smK + (kt * 16 + g * 8 + lq) * AST + lk;
#pragma unroll
                for (int e = 0; e < 4; e++) { sg[g][0][e] = 0.0f; sg[g][1][e] = 0.0f; }
#pragma unroll
                for (int ks = 0; ks < 4; ks++) {
                    u32 b0 = kb[ks * 8];
                    u32 b1 = kb[ks * 8 + 4];
                    mma_f16(sg[g][0][0], sg[g][0][1], sg[g][0][2], sg[g][0][3],
                            qf[0][ks][0], qf[0][ks][1], qf[0][ks][2], qf[0][ks][3], b0, b1);
                    mma_f16(sg[g][1][0], sg[g][1][1], sg[g][1][2], sg[g][1][3],
                            qf[1][ks][0], qf[1][ks][1], qf[1][ks][2], qf[1][ks][3], b0, b1);
                }
            }

            // ---- mask + exp + lsum + pack into P A-frags ----
            u32 pa[2][4];
#pragma unroll
            for (int mi = 0; mi < 2; mi++) {
                const int ra = qa0 + mi * 16;
                const int rb = ra + 8;
#pragma unroll
                for (int g = 0; g < 2; g++) {
                    const int jb = j0 + kt * 16 + g * 8 + 2 * lk;
                    float p0 = (jb     <= ra + 1) ? __expf(sg[g][mi][0] * SCEXP) : 0.0f;
                    float p1 = (jb + 1 <= ra + 1) ? __expf(sg[g][mi][1] * SCEXP) : 0.0f;
                    float p2 = (jb     <= rb + 1) ? __expf(sg[g][mi][2] * SCEXP) : 0.0f;
                    float p3 = (jb + 1 <= rb + 1) ? __expf(sg[g][mi][3] * SCEXP) : 0.0f;
                    ls[mi * 2]     += p0 + p1;
                    ls[mi * 2 + 1] += p2 + p3;
                    pa[mi][2 * g]     = pack16(p1, p0);
                    pa[mi][2 * g + 1] = pack16(p3, p2);
                }
            }

            // ---- O += P V (16-key k-step), B-frags shared across halves ----
#pragma unroll
            for (int ot = 0; ot < 8; ot++) {
                const u32* vb = smV + (ot * 8 + lq) * AST + kt * 8 + lk;
                u32 b0 = vb[0];
                u32 b1 = vb[4];
                mma_f16(oc[0][ot][0], oc[0][ot][1], oc[0][ot][2], oc[0][ot][3],
                        pa[0][0], pa[0][1], pa[0][2], pa[0][3], b0, b1);
                mma_f16(oc[1][ot][0], oc[1][ot][1], oc[1][ot][2], oc[1][ot][3],
                        pa[1][0], pa[1][1], pa[1][2], pa[1][3], b0, b1);
            }
        }
        __syncthreads();
    }

    // ---- write partial lsum (quad reduce); zeros if no tiles ----
#pragma unroll
    for (int i = 0; i < 4; i++) {
        ls[i] += __shfl_xor_sync(0xffffffffu, ls[i], 1);
        ls[i] += __shfl_xor_sync(0xffffffffu, ls[i], 2);
    }
    float* lp = g_l[part];
    if (lk == 0) {
        lp[(size_t)b * T_ + qa0]      = ls[0];
        lp[(size_t)b * T_ + qa0 + 8]  = ls[1];
        lp[(size_t)b * T_ + qa0 + 16] = ls[2];
        lp[(size_t)b * T_ + qa0 + 24] = ls[3];
    }

    // ---- write partial O (zeros if no tiles) ----
    float* pp = g_p[part];
#pragma unroll
    for (int mi = 0; mi < 2; mi++) {
        float* ra = pp + ((size_t)b * T_ + qa0 + mi * 16) * H_ + 2 * lk;
        float* rb = ra + (size_t)8 * H_;
#pragma unroll
        for (int ot = 0; ot < 8; ot++) {
            *(float2*)(ra + ot * 8) = make_float2(oc[mi][ot][0], oc[mi][ot][1]);
            *(float2*)(rb + ot * 8) = make_float2(oc[mi][ot][2], oc[mi][ot][3]);
        }
    }
    (void)dummy;
}

// =================================================================
// Kernel 3: combine 4 quarters + normalize.
// =================================================================
__global__ void __launch_bounds__(256) norm_out(float* __restrict__ out)
{
    int i4 = blockIdx.x * 256 + threadIdx.x;
    int row = i4 >> 4;
    float inv = 1.0f / (g_l[0][row] + g_l[1][row] + g_l[2][row] + g_l[3][row]);
    float4 a = ((const float4*)g_p[0])[i4];
    float4 c = ((const float4*)g_p[1])[i4];
    float4 d = ((const float4*)g_p[2])[i4];
    float4 e = ((const float4*)g_p[3])[i4];
    float4 o;
    o.x = (a.x + c.x + d.x + e.x) * inv;
    o.y = (a.y + c.y + d.y + e.y) * inv;
    o.z = (a.z + c.z + d.z + e.z) * inv;
    o.w = (a.w + c.w + d.w + e.w) * inv;
    ((float4*)out)[i4] = o;
}

// =================================================================
// launch
// =================================================================
extern "C" void kernel_launch(void* const* d_in, const int* in_sizes, int n_in,
                              void* d_out, int out_size)
{
    const float* x  = (const float*)d_in[0];
    const float* Wk = (const float*)d_in[1];
    const float* Wq = (const float*)d_in[2];
    const float* Wv = (const float*)d_in[3];
    float* out = (float*)d_out;

    (void)in_sizes; (void)n_in; (void)out_size;

    cudaFuncSetAttribute(proj_mma, cudaFuncAttributeMaxDynamicSharedMemorySize, PROJ_SMEM);
    cudaFuncSetAttribute(attn_mma, cudaFuncAttributeMaxDynamicSharedMemorySize, ATTN_SMEM);

    w_cvt<<<192, 256>>>(Wk, Wq, Wv);
    proj_mma<<<BT_ / 128, 256, PROJ_SMEM>>>(x);
    attn_mma<<<512, 128, ATTN_SMEM>>>(0);
    norm_out<<<(BT_ * H_ / 4) / 256, 256>>>(out);
}

// round 9
// speedup vs baseline: 6.1544x; 1.1670x over previous
#include <cuda_runtime.h>
#include <cuda_fp16.h>
#include <cstdint>

// Problem constants
#define B_  4
#define T_  4096
#define C_  1024
#define H_  64
#define BT_ (B_*T_)

typedef unsigned long long u64;
typedef unsigned int u32;

// Scratch — device globals, no allocation.
__device__ __half g_kh[(size_t)BT_ * H_];   // k, fp16 [b][t][h]
__device__ __half g_qh[(size_t)BT_ * H_];   // q, fp16 [b][t][h]
__device__ __half g_vt[(size_t)H_ * BT_];   // v^T, fp16 [h][b*T+t]
__device__ __half g_wh[192 * C_];           // fp16 W (k|q|v rows)
__device__ float  g_p[4][(size_t)BT_ * H_]; // partial O per key-quarter
__device__ float  g_l[4][(size_t)BT_];      // partial lsum per key-quarter

// ---------------- helpers ----------------
__device__ __forceinline__ u32 pack16(float hi, float lo) {
    u32 d; asm("cvt.rn.f16x2.f32 %0, %1, %2;" : "=r"(d) : "f"(hi), "f"(lo)); return d;
}
__device__ __forceinline__ u32 ex2h2(float hi, float lo) {
    u32 x = pack16(hi, lo);
    u32 y; asm("ex2.approx.f16x2 %0, %1;" : "=r"(y) : "r"(x));
    return y;
}
__device__ __forceinline__ void mma_f16(
    float& d0, float& d1, float& d2, float& d3,
    u32 a0, u32 a1, u32 a2, u32 a3, u32 b0, u32 b1)
{
    asm volatile(
        "mma.sync.aligned.m16n8k16.row.col.f32.f16.f16.f32 "
        "{%0,%1,%2,%3}, {%4,%5,%6,%7}, {%8,%9}, {%0,%1,%2,%3};"
        : "+f"(d0), "+f"(d1), "+f"(d2), "+f"(d3)
        : "r"(a0), "r"(a1), "r"(a2), "r"(a3), "r"(b0), "r"(b1));
}
__device__ __forceinline__ u32 smem_u32(const void* p) {
    u32 a;
    asm("{ .reg .u64 t; cvta.to.shared.u64 t, %1; cvt.u32.u64 %0, t; }" : "=r"(a) : "l"(p));
    return a;
}
#define LDSM4(R0, R1, R2, R3, A) \
    asm volatile("ldmatrix.sync.aligned.m8n8.x4.shared.b16 {%0,%1,%2,%3}, [%4];" \
        : "=r"(R0), "=r"(R1), "=r"(R2), "=r"(R3) : "r"(A))
#define CP16(dst, src) asm volatile("cp.async.ca.shared.global [%0], [%1], 16;" :: "r"(dst), "l"(src) : "memory")
#define CP_COMMIT()    asm volatile("cp.async.commit_group;" ::: "memory")
#define CP_WAIT0()     asm volatile("cp.async.wait_group 0;" ::: "memory")
#define CP_WAIT1()     asm volatile("cp.async.wait_group 1;" ::: "memory")

#define LOG2E64 0.02254211001389006f    /* log2(e)/64 */
#define NEGBIG  (-1e30f)

// =================================================================
// Kernel 0: convert W (Wk|Wq|Wv) to fp16, store concatenated.
// =================================================================
__global__ void __launch_bounds__(256) w_cvt(
    const float* __restrict__ Wk, const float* __restrict__ Wq,
    const float* __restrict__ Wv)
{
    int f = blockIdx.x * 256 + threadIdx.x;
    int head = f >> 14;
    int off  = f & 16383;
    const float4* src = (const float4*)(head == 0 ? Wk : (head == 1 ? Wq : Wv));
    float4 v = src[off];
    uint2 u;
    u.x = pack16(v.y, v.x);
    u.y = pack16(v.w, v.z);
    ((uint2*)g_wh)[f] = u;
}

// =================================================================
// Kernel 1: fused QKV projection, fp16 mma + ldmatrix frag loads.
// =================================================================
#define PST 36                                   // u32 stride per row
#define PROJ_STAGE ((128 + 192) * PST)
#define PROJ_SMEM  (PROJ_STAGE * 2 * 4)

__global__ void __launch_bounds__(256, 1) proj_mma(const float* __restrict__ x)
{
    extern __shared__ u32 psm[];
    const u32 smb = smem_u32(psm);

    const int tid  = threadIdx.x;
    const int w    = tid >> 5;
    const int lane = tid & 31;
    const int lq   = lane >> 2;
    const int lk   = lane & 3;
    const int grp  = lane >> 3;
    const int lrow = lane & 7;
    const int wrow = w >> 1;
    const int wcol = w & 1;
    const int m0   = blockIdx.x * 128;

    // ldmatrix per-lane bases (byte offsets)
    const u32 abase = (u32)((((grp & 1) * 8 + lrow) * PST + (grp >> 1) * 4) * 4);
    const u32 bbase = (u32)((((grp >> 1) * 8 + lrow) * PST + (grp & 1) * 4) * 4);
    const u32 xwarp = (u32)(wrow * 32 * PST * 4);
    const u32 wwarp = (u32)((128 + wcol * 96) * PST * 4);

    float acc[2][12][4];
#pragma unroll
    for (int mi = 0; mi < 2; mi++)
#pragma unroll
        for (int nt = 0; nt < 12; nt++)
#pragma unroll
            for (int e = 0; e < 4; e++) acc[mi][nt][e] = 0.0f;

#define PROJ_FILL(SB, CH) do {                                               \
    u32* xs_ = (SB);                                                         \
    u32  wsa_ = smem_u32((SB) + 128 * PST);                                  \
    _Pragma("unroll")                                                        \
    for (int i_ = 0; i_ < 6; i_++) {                                         \
        int idx_ = tid + i_ * 256;                                           \
        int r_ = idx_ >> 3, c8_ = idx_ & 7;                                  \
        CP16(wsa_ + (u32)(r_ * PST + c8_ * 4) * 4,                           \
             (const void*)(g_wh + (size_t)r_ * C_ + (CH) * 64 + c8_ * 8));   \
    }                                                                        \
    _Pragma("unroll")                                                        \
    for (int i_ = 0; i_ < 8; i_++) {                                         \
        int idx_ = tid + i_ * 256;                                           \
        int r_ = idx_ >> 4, c4_ = idx_ & 15;                                 \
        float4 v_ = *(const float4*)(x + (size_t)(m0 + r_) * C_ + (CH) * 64 + c4_ * 4); \
        uint2 u_;                                                            \
        u_.x = pack16(v_.y, v_.x);                                           \
        u_.y = pack16(v_.w, v_.z);                                           \
        *(uint2*)(xs_ + r_ * PST + c4_ * 2) = u_;                            \
    }                                                                        \
    CP_COMMIT();                                                             \
} while (0)

    PROJ_FILL(psm, 0);
    CP_WAIT0();
    __syncthreads();

    for (int ch = 0; ch < 16; ch++) {
        const int cur = ch & 1;
        if (ch + 1 < 16) {
            u32* nb = psm + ((ch + 1) & 1) * PROJ_STAGE;
            PROJ_FILL(nb, ch + 1);
        }
        {
            const u32 sbyte = smb + (u32)cur * (PROJ_STAGE * 4);
#pragma unroll
            for (int ks = 0; ks < 4; ks++) {
                u32 a[2][4];
                LDSM4(a[0][0], a[0][1], a[0][2], a[0][3],
                      sbyte + xwarp + abase + (u32)(ks * 32));
                LDSM4(a[1][0], a[1][1], a[1][2], a[1][3],
                      sbyte + xwarp + abase + (u32)(ks * 32 + 16 * PST * 4));
#pragma unroll
                for (int ntp = 0; ntp < 6; ntp++) {
                    u32 r0, r1, r2, r3;
                    LDSM4(r0, r1, r2, r3,
                          sbyte + wwarp + bbase + (u32)(ntp * 16 * PST * 4 + ks * 32));
                    mma_f16(acc[0][2*ntp][0], acc[0][2*ntp][1], acc[0][2*ntp][2], acc[0][2*ntp][3],
                            a[0][0], a[0][1], a[0][2], a[0][3], r0, r1);
                    mma_f16(acc[1][2*ntp][0], acc[1][2*ntp][1], acc[1][2*ntp][2], acc[1][2*ntp][3],
                            a[1][0], a[1][1], a[1][2], a[1][3], r0, r1);
                    mma_f16(acc[0][2*ntp+1][0], acc[0][2*ntp+1][1], acc[0][2*ntp+1][2], acc[0][2*ntp+1][3],
                            a[0][0], a[0][1], a[0][2], a[0][3], r2, r3);
                    mma_f16(acc[1][2*ntp+1][0], acc[1][2*ntp+1][1], acc[1][2*ntp+1][2], acc[1][2*ntp+1][3],
                            a[1][0], a[1][1], a[1][2], a[1][3], r2, r3);
                }
            }
        }
        if (ch + 1 < 16) CP_WAIT0();
        __syncthreads();
    }

    // ---- epilogue: fp16 round; k/q row-major, v transposed ----
#pragma unroll
    for (int mi = 0; mi < 2; mi++) {
#pragma unroll
        for (int nt = 0; nt < 12; nt++) {
            int gr = m0 + wrow * 32 + mi * 16 + lq;
            int gh = wcol * 96 + nt * 8 + 2 * lk;
            int head = gh >> 6;
            int hc   = gh & 63;
            if (head < 2) {
                __half* op = head ? g_qh : g_kh;
                *(u32*)(op + (size_t)gr * H_ + hc)       = pack16(acc[mi][nt][1], acc[mi][nt][0]);
                *(u32*)(op + (size_t)(gr + 8) * H_ + hc) = pack16(acc[mi][nt][3], acc[mi][nt][2]);
            } else {
                g_vt[(size_t)hc * BT_ + gr]           = __float2half_rn(acc[mi][nt][0]);
                g_vt[(size_t)(hc + 1) * BT_ + gr]     = __float2half_rn(acc[mi][nt][1]);
                g_vt[(size_t)hc * BT_ + gr + 8]       = __float2half_rn(acc[mi][nt][2]);
                g_vt[(size_t)(hc + 1) * BT_ + gr + 8] = __float2half_rn(acc[mi][nt][3]);
            }
        }
    }
}

// =================================================================
// Kernel 2: attention. fp16 mma, ldmatrix frags, ex2.f16x2 softmax,
//   lsum via ones-column MMA. 4 warps x 32 q-rows, 4-way split-K,
//   64-key tiles, double-buffered cp.async.
// =================================================================
#define KTILE 64
#define AST 36                                    // u32 row stride
#define STG_WORDS (KTILE * AST * 2)               // K + V^T per stage
#define STG_BYTES (STG_WORDS * 4)
#define ATTN_SMEM (STG_BYTES * 2)

__global__ void __launch_bounds__(128, 3) attn_mma(int dummy)
{
    extern __shared__ u32 smw[];
    const u32 smb = smem_u32(smw);

    const int tid  = threadIdx.x;
    const int w    = tid >> 5;
    const int lane = tid & 31;
    const int lq   = lane >> 2;
    const int lk   = lane & 3;
    const int grp  = lane >> 3;
    const int lrow = lane & 7;

    const int part = blockIdx.x & 3;
    const int pid  = blockIdx.x >> 2;
    const int b    = pid & 3;
    const int mblk = 31 - (pid >> 2);      // heavy first
    const int m0   = mblk * 128;

    const int nkt = min(2 * mblk + 3, T_ / KTILE);
    const int t_beg = (nkt * part) >> 2;
    const int t_end = (nkt * (part + 1)) >> 2;

    const int qbase = m0 + w * 32;
    const int qa0   = qbase + lq;

    // ldmatrix per-lane base (shared by K and V regions)
    const u32 lmb = (u32)(((((grp >> 1) * 8 + lrow) * AST) + (grp & 1) * 4) * 4);
    // ones-column B-frag for lsum MMA
    const u32 bone = (lq == 0) ? 0x3C003C00u : 0u;

    // ---- Q A-frags fp16, 4 k-steps x 2 row-halves ----
    u32 qf[2][4][4];
#pragma unroll
    for (int mi = 0; mi < 2; mi++) {
        const u32* qp = (const u32*)(g_qh + ((size_t)b * T_ + qa0 + mi * 16) * H_) + lk;
#pragma unroll
        for (int ks = 0; ks < 4; ks++) {
            qf[mi][ks][0] = qp[ks * 8];
            qf[mi][ks][1] = qp[8 * 32 + ks * 8];
            qf[mi][ks][2] = qp[ks * 8 + 4];
            qf[mi][ks][3] = qp[8 * 32 + ks * 8 + 4];
        }
    }

    float oc[2][9][4];     // [..][8] = lsum column accumulator
#pragma unroll
    for (int mi = 0; mi < 2; mi++)
#pragma unroll
        for (int i = 0; i < 9; i++)
#pragma unroll
            for (int j = 0; j < 4; j++) oc[mi][i][j] = 0.0f;

#define ATTN_FILL(STG, T) do {                                               \
    const __half* kg_ = g_kh + ((size_t)b * T_ + (size_t)(T) * KTILE) * H_;  \
    const __half* vg_ = g_vt + (size_t)b * T_ + (size_t)(T) * KTILE;         \
    u32 base_ = smb + (u32)(STG) * STG_BYTES;                                \
    _Pragma("unroll")                                                        \
    for (int i_ = 0; i_ < 4; i_++) {                                         \
        int idx_ = tid + i_ * 128;                                           \
        int r_ = idx_ >> 3, c8_ = idx_ & 7;                                  \
        CP16(base_ + (u32)(r_ * AST + c8_ * 4) * 4,                          \
             (const void*)(kg_ + (size_t)r_ * H_ + c8_ * 8));                \
        CP16(base_ + (u32)(KTILE * AST + r_ * AST + c8_ * 4) * 4,            \
             (const void*)(vg_ + (size_t)r_ * BT_ + c8_ * 8));               \
    }                                                                        \
    CP_COMMIT();                                                             \
} while (0)

    if (t_beg < t_end) ATTN_FILL(t_beg & 1, t_beg);

    for (int t = t_beg; t < t_end; t++) {
        const int j0 = t * KTILE;
        const bool pre = (t + 1 < t_end);
        if (pre) {
            ATTN_FILL((t + 1) & 1, t + 1);
            CP_WAIT1();
        } else {
            CP_WAIT0();
        }
        __syncthreads();

        const u32 kbyte = smb + (u32)(t & 1) * STG_BYTES;
        const u32 vbyte = kbyte + (u32)(KTILE * AST * 4);

        const int ktmax = min(3, (qbase + 32 - j0) >> 4);
        for (int kt = 0; kt <= ktmax; kt++) {
            // ---- S c-frags: 16 keys (2 groups) x 2 row-halves ----
            float sg[2][2][4];
#pragma unroll
            for (int g = 0; g < 2; g++)
#pragma unroll
                for (int mi = 0; mi < 2; mi++)
#pragma unroll
                    for (int e = 0; e < 4; e++) sg[g][mi][e] = 0.0f;
#pragma unroll
            for (int ks = 0; ks < 4; ks++) {
                u32 kb0, kb1, kb2, kb3;
                LDSM4(kb0, kb1, kb2, kb3,
                      kbyte + lmb + (u32)(kt * 16 * AST * 4 + ks * 32));
                mma_f16(sg[0][0][0], sg[0][0][1], sg[0][0][2], sg[0][0][3],
                        qf[0][ks][0], qf[0][ks][1], qf[0][ks][2], qf[0][ks][3], kb0, kb1);
                mma_f16(sg[0][1][0], sg[0][1][1], sg[0][1][2], sg[0][1][3],
                        qf[1][ks][0], qf[1][ks][1], qf[1][ks][2], qf[1][ks][3], kb0, kb1);
                mma_f16(sg[1][0][0], sg[1][0][1], sg[1][0][2], sg[1][0][3],
                        qf[0][ks][0], qf[0][ks][1], qf[0][ks][2], qf[0][ks][3], kb2, kb3);
                mma_f16(sg[1][1][0], sg[1][1][1], sg[1][1][2], sg[1][1][3],
                        qf[1][ks][0], qf[1][ks][1], qf[1][ks][2], qf[1][ks][3], kb2, kb3);
            }

            // ---- softmax: mask, scale to log2 domain, ex2.f16x2 ----
            u32 pa[2][4];
#pragma unroll
            for (int mi = 0; mi < 2; mi++) {
                const int ra = qa0 + mi * 16;
                const int rb = ra + 8;
#pragma unroll
                for (int g = 0; g < 2; g++) {
                    const int jb = j0 + kt * 16 + g * 8 + 2 * lk;
                    float e0 = (jb     <= ra + 1) ? sg[g][mi][0] * LOG2E64 : NEGBIG;
                    float e1 = (jb + 1 <= ra + 1) ? sg[g][mi][1] * LOG2E64 : NEGBIG;
                    float e2 = (jb     <= rb + 1) ? sg[g][mi][2] * LOG2E64 : NEGBIG;
                    float e3 = (jb + 1 <= rb + 1) ? sg[g][mi][3] * LOG2E64 : NEGBIG;
                    pa[mi][2 * g]     = ex2h2(e1, e0);
                    pa[mi][2 * g + 1] = ex2h2(e3, e2);
                }
            }

            // ---- O += P V ; lsum via ones-column MMA ----
#pragma unroll
            for (int otp = 0; otp < 4; otp++) {
                u32 v0, v1, v2, v3;
                LDSM4(v0, v1, v2, v3,
                      vbyte + lmb + (u32)(otp * 16 * AST * 4 + kt * 32));
                mma_f16(oc[0][2*otp][0], oc[0][2*otp][1], oc[0][2*otp][2], oc[0][2*otp][3],
                        pa[0][0], pa[0][1], pa[0][2], pa[0][3], v0, v1);
                mma_f16(oc[1][2*otp][0], oc[1][2*otp][1], oc[1][2*otp][2], oc[1][2*otp][3],
                        pa[1][0], pa[1][1], pa[1][2], pa[1][3], v0, v1);
                mma_f16(oc[0][2*otp+1][0], oc[0][2*otp+1][1], oc[0][2*otp+1][2], oc[0][2*otp+1][3],
                        pa[0][0], pa[0][1], pa[0][2], pa[0][3], v2, v3);
                mma_f16(oc[1][2*otp+1][0], oc[1][2*otp+1][1], oc[1][2*otp+1][2], oc[1][2*otp+1][3],
                        pa[1][0], pa[1][1], pa[1][2], pa[1][3], v2, v3);
            }
            mma_f16(oc[0][8][0], oc[0][8][1], oc[0][8][2], oc[0][8][3],
                    pa[0][0], pa[0][1], pa[0][2], pa[0][3], bone, bone);
            mma_f16(oc[1][8][0], oc[1][8][1], oc[1][8][2], oc[1][8][3],
                    pa[1][0], pa[1][1], pa[1][2], pa[1][3], bone, bone);
        }
        __syncthreads();
    }

    // ---- write partial lsum (column 0 of ones-MMA C-frag) ----
    float* lp = g_l[part];
    if (lk == 0) {
        lp[(size_t)b * T_ + qa0]      = oc[0][8][0];
        lp[(size_t)b * T_ + qa0 + 8]  = oc[0][8][2];
        lp[(size_t)b * T_ + qa0 + 16] = oc[1][8][0];
        lp[(size_t)b * T_ + qa0 + 24] = oc[1][8][2];
    }

    // ---- write partial O ----
    float* pp = g_p[part];
#pragma unroll
    for (int mi = 0; mi < 2; mi++) {
        float* ra = pp + ((size_t)b * T_ + qa0 + mi * 16) * H_ + 2 * lk;
        float* rb = ra + (size_t)8 * H_;
#pragma unroll
        for (int ot = 0; ot < 8; ot++) {
            *(float2*)(ra + ot * 8) = make_float2(oc[mi][ot][0], oc[mi][ot][1]);
            *(float2*)(rb + ot * 8) = make_float2(oc[mi][ot][2], oc[mi][ot][3]);
        }
    }
    (void)dummy;
}

// =================================================================
// Kernel 3: combine 4 quarters + normalize.
// =================================================================
__global__ void __launch_bounds__(256) norm_out(float* __restrict__ out)
{
    int i4 = blockIdx.x * 256 + threadIdx.x;
    int row = i4 >> 4;
    float inv = 1.0f / (g_l[0][row] + g_l[1][row] + g_l[2][row] + g_l[3][row]);
    float4 a = ((const float4*)g_p[0])[i4];
    float4 c = ((const float4*)g_p[1])[i4];
    float4 d = ((const float4*)g_p[2])[i4];
    float4 e = ((const float4*)g_p[3])[i4];
    float4 o;
    o.x = (a.x + c.x + d.x + e.x) * inv;
    o.y = (a.y + c.y + d.y + e.y) * inv;
    o.z = (a.z + c.z + d.z + e.z) * inv;
    o.w = (a.w + c.w + d.w + e.w) * inv;
    ((float4*)out)[i4] = o;
}

// =================================================================
// launch
// =================================================================
extern "C" void kernel_launch(void* const* d_in, const int* in_sizes, int n_in,
                              void* d_out, int out_size)
{
    const float* x  = (const float*)d_in[0];
    const float* Wk = (const float*)d_in[1];
    const float* Wq = (const float*)d_in[2];
    const float* Wv = (const float*)d_in[3];
    float* out = (float*)d_out;

    (void)in_sizes; (void)n_in; (void)out_size;

    cudaFuncSetAttribute(proj_mma, cudaFuncAttributeMaxDynamicSharedMemorySize, PROJ_SMEM);
    cudaFuncSetAttribute(attn_mma, cudaFuncAttributeMaxDynamicSharedMemorySize, ATTN_SMEM);

    w_cvt<<<192, 256>>>(Wk, Wq, Wv);
    proj_mma<<<BT_ / 128, 256, PROJ_SMEM>>>(x);
    attn_mma<<<512, 128, ATTN_SMEM>>>(0);
    norm_out<<<(BT_ * H_ / 4) / 256, 256>>>(out);
}